// round 10
// baseline (speedup 1.0000x reference)
#include <cuda_runtime.h>
#include <cuda_bf16.h>
#include <cstdint>

// ---------------- model dims ----------------
#define BATCH 2
#define SEQ   2048
#define TOK   (BATCH*SEQ)        // 4096
#define HID   2048
#define NK    16
#define NV    32
#define DK    128
#define DV    128
#define KEYD  2048               // NK*DK
#define VALD  4096               // NV*DV
#define CONVD 8192               // 2*KEYD + VALD
#define PQKVZ 12288              // 2*KEYD + 2*VALD
#define EPSF  1e-6f

// ---------------- scratch (device globals; no allocation) ----------------
__device__ float g_qkvz [(size_t)TOK * PQKVZ];
__device__ float g_ba   [(size_t)TOK * 64];
__device__ float g_conv [(size_t)TOK * CONVD];
__device__ float g_qn   [(size_t)TOK * KEYD];
__device__ float g_kn   [(size_t)TOK * KEYD];
__device__ float g_beta [(size_t)TOK * NV];
__device__ float g_gdec [(size_t)TOK * NV];
__device__ float g_core [(size_t)TOK * VALD];
// bf16 hi/lo split scratch
__device__ __nv_bfloat16 g_xhi [(size_t)TOK * HID];
__device__ __nv_bfloat16 g_xlo [(size_t)TOK * HID];
__device__ __nv_bfloat16 g_w1hi[(size_t)PQKVZ * HID];
__device__ __nv_bfloat16 g_w1lo[(size_t)PQKVZ * HID];
__device__ __nv_bfloat16 g_w2hi[(size_t)HID * VALD];
__device__ __nv_bfloat16 g_w2lo[(size_t)HID * VALD];
__device__ __nv_bfloat16 g_ghi [(size_t)TOK * VALD];
__device__ __nv_bfloat16 g_glo [(size_t)TOK * VALD];

// ---------------- helpers ----------------
__device__ __forceinline__ uint32_t smem_u32(const void* p) {
    uint32_t r;
    asm("{ .reg .u64 t; cvta.to.shared.u64 t, %1; cvt.u32.u64 %0, t; }" : "=r"(r) : "l"(p));
    return r;
}
__device__ __forceinline__ void cpasync16(uint32_t s, const void* g) {
    asm volatile("cp.async.cg.shared.global [%0], [%1], 16;" :: "r"(s), "l"(g));
}
__device__ __forceinline__ void cpasync4(uint32_t s, const void* g) {
    asm volatile("cp.async.ca.shared.global [%0], [%1], 4;" :: "r"(s), "l"(g));
}
__device__ __forceinline__ void ldmx4(uint32_t* r, uint32_t addr) {
    asm volatile("ldmatrix.sync.aligned.m8n8.x4.shared.b16 {%0,%1,%2,%3}, [%4];"
                 : "=r"(r[0]), "=r"(r[1]), "=r"(r[2]), "=r"(r[3]) : "r"(addr));
}
__device__ __forceinline__ void mma16816(float* c, const uint32_t* a, const uint32_t* b) {
    asm volatile(
        "mma.sync.aligned.m16n8k16.row.col.f32.bf16.bf16.f32 "
        "{%0,%1,%2,%3}, {%4,%5,%6,%7}, {%8,%9}, {%0,%1,%2,%3};"
        : "+f"(c[0]), "+f"(c[1]), "+f"(c[2]), "+f"(c[3])
        : "r"(a[0]), "r"(a[1]), "r"(a[2]), "r"(a[3]), "r"(b[0]), "r"(b[1]));
}
// f32x2 packed math
__device__ __forceinline__ unsigned long long pk2(float a, float b) {
    unsigned long long r; asm("mov.b64 %0, {%1, %2};" : "=l"(r) : "f"(a), "f"(b)); return r;
}
__device__ __forceinline__ unsigned long long fma2(unsigned long long a, unsigned long long b, unsigned long long c) {
    unsigned long long d; asm("fma.rn.f32x2 %0, %1, %2, %3;" : "=l"(d) : "l"(a), "l"(b), "l"(c)); return d;
}
__device__ __forceinline__ unsigned long long mul2(unsigned long long a, unsigned long long b) {
    unsigned long long d; asm("mul.rn.f32x2 %0, %1, %2;" : "=l"(d) : "l"(a), "l"(b)); return d;
}
__device__ __forceinline__ float hadd2(unsigned long long v) {
    float a, b; asm("mov.b64 {%0, %1}, %2;" : "=f"(a), "=f"(b) : "l"(v)); return a + b;
}

// ---------------- split fp32 -> bf16 hi/lo ----------------
__global__ __launch_bounds__(256) void split_bf16(const float* __restrict__ src,
                                                  __nv_bfloat16* __restrict__ hi,
                                                  __nv_bfloat16* __restrict__ lo) {
    size_t i = ((size_t)blockIdx.x * blockDim.x + threadIdx.x) * 4;
    float4 v = *(const float4*)(src + i);
    __nv_bfloat16 h0 = __float2bfloat16(v.x), h1 = __float2bfloat16(v.y);
    __nv_bfloat16 h2 = __float2bfloat16(v.z), h3 = __float2bfloat16(v.w);
    __nv_bfloat16 l0 = __float2bfloat16(v.x - __bfloat162float(h0));
    __nv_bfloat16 l1 = __float2bfloat16(v.y - __bfloat162float(h1));
    __nv_bfloat16 l2 = __float2bfloat16(v.z - __bfloat162float(h2));
    __nv_bfloat16 l3 = __float2bfloat16(v.w - __bfloat162float(h3));
    __nv_bfloat162* hp = (__nv_bfloat162*)(hi + i);
    __nv_bfloat162* lp = (__nv_bfloat162*)(lo + i);
    hp[0] = __nv_bfloat162(h0, h1); hp[1] = __nv_bfloat162(h2, h3);
    lp[0] = __nv_bfloat162(l0, l1); lp[1] = __nv_bfloat162(l2, l3);
}

// ---------------- mma.sync bf16x3 GEMM (NT): C[m,n] = sum_k A[m,k]*B[n,k] ----------------
#define TSTRIDE 80
#define TILE_B  (128 * TSTRIDE)
#define STAGE_B (4 * TILE_B)
#define GSMEM   (2 * STAGE_B)

__global__ __launch_bounds__(256, 2)
void gemm_bf16x3(const __nv_bfloat16* __restrict__ Ah, const __nv_bfloat16* __restrict__ Al,
                 const __nv_bfloat16* __restrict__ Bh, const __nv_bfloat16* __restrict__ Bl,
                 float* __restrict__ C, int M, int N, int K) {
    extern __shared__ char sm[];
    const uint32_t sb = smem_u32(sm);
    const int tid = threadIdx.x;
    const int lane = tid & 31, wid = tid >> 5;
    const int bm = blockIdx.x * 128, bn = blockIdx.y * 128;
    const int wm = (wid & 1) * 64, wn = (wid >> 1) * 32;
    const int grp = lane >> 2, qid = lane & 3;

    const uint32_t a_row = (uint32_t)(lane & 15);
    const uint32_t a_c16 = (uint32_t)((lane >> 4) * 16);
    const uint32_t b_row = (uint32_t)((lane & 7) + ((lane >> 4) & 1) * 8);
    const uint32_t b_c16 = (uint32_t)(((lane >> 3) & 1) * 16);

    float c[4][4][4];
    #pragma unroll
    for (int i = 0; i < 4; i++)
        #pragma unroll
        for (int j = 0; j < 4; j++)
            #pragma unroll
            for (int r = 0; r < 4; r++) c[i][j][r] = 0.f;

    const int niter = K >> 5;

    auto issue = [&](int kblk, int buf) {
        const int k0 = kblk * 32;
        #pragma unroll
        for (int i = 0; i < 2; i++) {
            int chunk = tid + i * 256;
            int row = chunk >> 2, c16 = chunk & 3;
            size_t ga = (size_t)(bm + row) * K + k0 + c16 * 8;
            size_t gb = (size_t)(bn + row) * K + k0 + c16 * 8;
            uint32_t so = sb + buf * STAGE_B + row * TSTRIDE + c16 * 16;
            cpasync16(so,              Ah + ga);
            cpasync16(so + TILE_B,     Al + ga);
            cpasync16(so + 2 * TILE_B, Bh + gb);
            cpasync16(so + 3 * TILE_B, Bl + gb);
        }
    };

    issue(0, 0);
    asm volatile("cp.async.commit_group;" ::: "memory");
    issue(1, 1);
    asm volatile("cp.async.commit_group;" ::: "memory");

    for (int it = 0; it < niter; it++) {
        asm volatile("cp.async.wait_group 1;" ::: "memory");
        __syncthreads();
        const int buf = it & 1;
        const uint32_t base = sb + buf * STAGE_B;

        #pragma unroll
        for (int ks = 0; ks < 2; ks++) {
            const uint32_t koff = ks * 32;
            const uint32_t abase = base + (uint32_t)(wm + a_row) * TSTRIDE + koff + a_c16;
            const uint32_t bbase = base + 2 * TILE_B + (uint32_t)(wn + b_row) * TSTRIDE + koff + b_c16;
            uint32_t ah[4][4], bh[2][4];
            #pragma unroll
            for (int i = 0; i < 4; i++) ldmx4(ah[i], abase + (uint32_t)(i * 16) * TSTRIDE);
            #pragma unroll
            for (int J = 0; J < 2; J++) ldmx4(bh[J], bbase + (uint32_t)(J * 16) * TSTRIDE);
            // phase 1: hh
            #pragma unroll
            for (int i = 0; i < 4; i++)
                #pragma unroll
                for (int j = 0; j < 4; j++) mma16816(c[i][j], ah[i], &bh[j >> 1][(j & 1) * 2]);
            // phase 2: lh
            {
                uint32_t al[4][4];
                #pragma unroll
                for (int i = 0; i < 4; i++) ldmx4(al[i], abase + TILE_B + (uint32_t)(i * 16) * TSTRIDE);
                #pragma unroll
                for (int i = 0; i < 4; i++)
                    #pragma unroll
                    for (int j = 0; j < 4; j++) mma16816(c[i][j], al[i], &bh[j >> 1][(j & 1) * 2]);
            }
            // phase 3: hl
            {
                uint32_t bl[2][4];
                #pragma unroll
                for (int J = 0; J < 2; J++) ldmx4(bl[J], bbase + TILE_B + (uint32_t)(J * 16) * TSTRIDE);
                #pragma unroll
                for (int i = 0; i < 4; i++)
                    #pragma unroll
                    for (int j = 0; j < 4; j++) mma16816(c[i][j], ah[i], &bl[j >> 1][(j & 1) * 2]);
            }
        }
        __syncthreads();
        if (it + 2 < niter) issue(it + 2, buf);
        asm volatile("cp.async.commit_group;" ::: "memory");
    }

    #pragma unroll
    for (int i = 0; i < 4; i++) {
        const int row0 = bm + wm + i * 16 + grp;
        #pragma unroll
        for (int j = 0; j < 4; j++) {
            const int col = bn + wn + j * 8 + qid * 2;
            float2 v01 = make_float2(c[i][j][0], c[i][j][1]);
            float2 v23 = make_float2(c[i][j][2], c[i][j][3]);
            *(float2*)(C + (size_t)row0 * N + col)       = v01;
            *(float2*)(C + (size_t)(row0 + 8) * N + col) = v23;
        }
    }
}

// ---------------- SIMT SGEMM (NT) for tiny ba GEMM ----------------
#define BM 128
#define BN 128
#define BKK 16
__global__ __launch_bounds__(256) void sgemm_nt(const float* __restrict__ A,
                                                const float* __restrict__ B,
                                                float* __restrict__ C,
                                                int M, int N, int K) {
    __shared__ float As[BKK][BM];
    __shared__ float Bs[BKK][BN];
    const int tid = threadIdx.x;
    const int bm = blockIdx.y * BM;
    const int bn = blockIdx.x * BN;
    const int tx = tid & 15;
    const int ty = tid >> 4;
    const int lrow = tid >> 2;
    const int lk4 = (tid & 3) * 4;

    float acc[8][8];
    #pragma unroll
    for (int i = 0; i < 8; i++)
        #pragma unroll
        for (int j = 0; j < 8; j++) acc[i][j] = 0.f;

    for (int k0 = 0; k0 < K; k0 += BKK) {
        #pragma unroll
        for (int it = 0; it < 2; it++) {
            int row = lrow + it * 64;
            float4 v = *(const float4*)(A + (size_t)(bm + row) * K + k0 + lk4);
            As[lk4 + 0][row] = v.x; As[lk4 + 1][row] = v.y;
            As[lk4 + 2][row] = v.z; As[lk4 + 3][row] = v.w;
        }
        #pragma unroll
        for (int it = 0; it < 2; it++) {
            int row = lrow + it * 64;
            int gn = bn + row;
            float4 v = make_float4(0.f, 0.f, 0.f, 0.f);
            if (gn < N) v = *(const float4*)(B + (size_t)gn * K + k0 + lk4);
            Bs[lk4 + 0][row] = v.x; Bs[lk4 + 1][row] = v.y;
            Bs[lk4 + 2][row] = v.z; Bs[lk4 + 3][row] = v.w;
        }
        __syncthreads();
        #pragma unroll
        for (int kk = 0; kk < BKK; kk++) {
            float ar[8], br[8];
            #pragma unroll
            for (int i = 0; i < 8; i++) ar[i] = As[kk][ty * 8 + i];
            #pragma unroll
            for (int j = 0; j < 8; j++) br[j] = Bs[kk][tx * 8 + j];
            #pragma unroll
            for (int i = 0; i < 8; i++)
                #pragma unroll
                for (int j = 0; j < 8; j++)
                    acc[i][j] = fmaf(ar[i], br[j], acc[i][j]);
        }
        __syncthreads();
    }
    #pragma unroll
    for (int i = 0; i < 8; i++) {
        int gm = bm + ty * 8 + i;
        #pragma unroll
        for (int j = 0; j < 8; j++) {
            int gn = bn + tx * 8 + j;
            if (gn < N) C[(size_t)gm * N + gn] = acc[i][j];
        }
    }
}

// ---------------- depthwise causal conv1d (K=4) + SiLU ----------------
__global__ void conv_silu_kernel(const float* __restrict__ qkvz,
                                 const float* __restrict__ cw,
                                 float* __restrict__ out) {
    size_t idx = (size_t)blockIdx.x * blockDim.x + threadIdx.x;
    int c = (int)(idx & (CONVD - 1));
    size_t t = idx >> 13;
    int s = (int)(t & (SEQ - 1));
    size_t b = t >> 11;
    const float* base = qkvz + (b * SEQ) * (size_t)PQKVZ + c;
    float w0 = cw[c * 4 + 0], w1 = cw[c * 4 + 1], w2 = cw[c * 4 + 2], w3 = cw[c * 4 + 3];
    float acc = w3 * base[(size_t)s * PQKVZ];
    if (s >= 1) acc = fmaf(w2, base[(size_t)(s - 1) * PQKVZ], acc);
    if (s >= 2) acc = fmaf(w1, base[(size_t)(s - 2) * PQKVZ], acc);
    if (s >= 3) acc = fmaf(w0, base[(size_t)(s - 3) * PQKVZ], acc);
    out[idx] = acc / (1.f + expf(-acc));
}

// ---------------- l2norm(q,k) + gates ----------------
__global__ __launch_bounds__(512) void prep_kernel(const float* __restrict__ conv,
                                                   const float* __restrict__ ba,
                                                   const float* __restrict__ dt_bias,
                                                   const float* __restrict__ A_log,
                                                   float* __restrict__ qn,
                                                   float* __restrict__ kn,
                                                   float* __restrict__ beta,
                                                   float* __restrict__ gdec) {
    size_t t = blockIdx.x;
    int w = threadIdx.x >> 5;
    int l = threadIdx.x & 31;
    const float* cq = conv + t * CONVD + w * DK;
    const float* ck = conv + t * CONVD + KEYD + w * DK;
    float qv[4], kv[4];
    float sq = 0.f, sk = 0.f;
    #pragma unroll
    for (int i = 0; i < 4; i++) {
        qv[i] = cq[l + 32 * i]; sq = fmaf(qv[i], qv[i], sq);
        kv[i] = ck[l + 32 * i]; sk = fmaf(kv[i], kv[i], sk);
    }
    #pragma unroll
    for (int o = 16; o; o >>= 1) {
        sq += __shfl_xor_sync(0xffffffffu, sq, o);
        sk += __shfl_xor_sync(0xffffffffu, sk, o);
    }
    float rq = rsqrtf(sq + EPSF), rk = rsqrtf(sk + EPSF);
    #pragma unroll
    for (int i = 0; i < 4; i++) {
        qn[(t * NK + w) * DK + l + 32 * i] = qv[i] * rq;
        kn[(t * NK + w) * DK + l + 32 * i] = kv[i] * rk;
    }
    if (threadIdx.x < NV) {
        int h = threadIdx.x;
        float bv = ba[t * 64 + h];
        float av = ba[t * 64 + NV + h];
        beta[t * NV + h] = 1.f / (1.f + expf(-bv));
        float xx = av + dt_bias[h];
        float sp = (xx > 20.f) ? xx : log1pf(expf(xx));
        gdec[t * NV + h] = expf(-expf(A_log[h]) * sp);
    }
}

// ---------------- gated delta-rule scan v7: 8 threads/col, 4 warps/SMSP ----------------
// Grid (NV, 2, BATCH) = 128 CTAs; 512 threads: 8 per DV column (DK eighths of 16 floats).
// Eighth-group smem padding: group g at float offset g*20 (80B) -> conflict-free LDS.
#define SCH   8
#define KGRP  20    // 16 data + 4 pad floats per eighth
#define KROW  160   // 8 * KGRP
__global__ __launch_bounds__(512) void scan_kernel(const float* __restrict__ qn,
                                                   const float* __restrict__ kn,
                                                   const float* __restrict__ conv,
                                                   const float* __restrict__ beta,
                                                   const float* __restrict__ gdec,
                                                   float* __restrict__ core) {
    const int h = blockIdx.x;        // value head
    const int dv0 = blockIdx.y * 64; // DV half
    const int b = blockIdx.z;
    const int nk = h >> 1;
    const int tid = threadIdx.x;
    const int col = tid >> 3;        // local DV col 0..63
    const int e8 = tid & 7;          // DK eighth
    __shared__ float ksm[2][SCH][KROW];
    __shared__ float qsm[2][SCH][KROW];
    __shared__ float vsm[2][SCH][64];
    __shared__ float gsm[2][SCH], bsm[2][SCH];

    unsigned long long st[8];        // 16 floats of state (this eighth x this col)
    #pragma unroll
    for (int j = 0; j < 8; j++) st[j] = 0ull;

    const size_t tbase = (size_t)b * SEQ;
    // loader roles
    const int kr = (tid >> 5) & 7;           // row 0..7 (k for tid<256, q for tid>=256)
    const int kl = tid & 31;                 // lane within row
    const int kqoff = (kl >> 2) * KGRP + (kl & 3) * 4;  // padded dst float offset

    auto issue = [&](int blk, int buf) {
        const size_t t0 = tbase + (size_t)blk * SCH;
        if (tid < 256)
            cpasync16(smem_u32(&ksm[buf][kr][kqoff]), kn + ((t0 + kr) * NK + nk) * DK + kl * 4);
        else
            cpasync16(smem_u32(&qsm[buf][kr][kqoff]), qn + ((t0 + kr) * NK + nk) * DK + kl * 4);
        if (tid < 128) {
            int vr = tid >> 4, vc = (tid & 15) * 4;
            cpasync16(smem_u32(&vsm[buf][vr][vc]),
                      conv + (t0 + vr) * CONVD + 2 * KEYD + h * DV + dv0 + vc);
        } else if (tid < 128 + SCH) {
            cpasync4(smem_u32(&gsm[buf][tid - 128]), gdec + (t0 + tid - 128) * NV + h);
        } else if (tid < 128 + 2 * SCH) {
            cpasync4(smem_u32(&bsm[buf][tid - 128 - SCH]), beta + (t0 + tid - 128 - SCH) * NV + h);
        }
    };

    issue(0, 0);
    asm volatile("cp.async.commit_group;" ::: "memory");
    issue(1, 1);
    asm volatile("cp.async.commit_group;" ::: "memory");

    const int nblk = SEQ / SCH;
    for (int blk = 0; blk < nblk; blk++) {
        const int buf = blk & 1;
        asm volatile("cp.async.wait_group 1;" ::: "memory");
        __syncthreads();

        #pragma unroll
        for (int i = 0; i < SCH; i++) {
            const ulonglong2* kk = (const ulonglong2*)&ksm[buf][i][e8 * KGRP];
            const ulonglong2* qq = (const ulonglong2*)&qsm[buf][i][e8 * KGRP];
            float vt = vsm[buf][i][col];
            float ge = gsm[buf][i];
            float bt = bsm[buf][i];

            unsigned long long a0 = 0ull, a1 = 0ull;
            #pragma unroll
            for (int j = 0; j < 4; j++) {
                ulonglong2 kj = kk[j];
                a0 = fma2(kj.x, st[2 * j + 0], a0);
                a1 = fma2(kj.y, st[2 * j + 1], a1);
            }
            float kvd = hadd2(a0) + hadd2(a1);
            kvd += __shfl_xor_sync(0xffffffffu, kvd, 1);
            kvd += __shfl_xor_sync(0xffffffffu, kvd, 2);
            kvd += __shfl_xor_sync(0xffffffffu, kvd, 4);
            float delta = bt * (vt - ge * kvd);
            unsigned long long ge2 = pk2(ge, ge);
            unsigned long long d2 = pk2(delta, delta);

            unsigned long long o0 = 0ull, o1 = 0ull;
            #pragma unroll
            for (int j = 0; j < 4; j++) {
                ulonglong2 kj = kk[j], qj = qq[j];
                st[2 * j + 0] = fma2(ge2, st[2 * j + 0], mul2(kj.x, d2));
                o0 = fma2(qj.x, st[2 * j + 0], o0);
                st[2 * j + 1] = fma2(ge2, st[2 * j + 1], mul2(kj.y, d2));
                o1 = fma2(qj.y, st[2 * j + 1], o1);
            }
            float o = hadd2(o0) + hadd2(o1);
            o += __shfl_xor_sync(0xffffffffu, o, 1);
            o += __shfl_xor_sync(0xffffffffu, o, 2);
            o += __shfl_xor_sync(0xffffffffu, o, 4);
            if (e8 == 0)
                core[(tbase + (size_t)blk * SCH + i) * VALD + h * DV + dv0 + col] = o;
        }

        __syncthreads();
        if (blk + 2 < nblk) issue(blk + 2, buf);
        asm volatile("cp.async.commit_group;" ::: "memory");
    }
}

// ---------------- RMSNorm(1+w) + silu(z) gate -> bf16 hi/lo ----------------
__global__ __launch_bounds__(256) void rmsnorm_gate_kernel(const float* __restrict__ core,
                                                           const float* __restrict__ qkvz,
                                                           const float* __restrict__ norm_w,
                                                           __nv_bfloat16* __restrict__ ghi,
                                                           __nv_bfloat16* __restrict__ glo) {
    size_t t = blockIdx.x;
    __shared__ float red[8];
    __shared__ float s_scale;
    const float* row = core + t * VALD;
    const float* zrow = qkvz + t * PQKVZ + 2 * KEYD + VALD;
    float ss = 0.f;
    for (int c = threadIdx.x; c < VALD; c += 256) { float v = row[c]; ss = fmaf(v, v, ss); }
    #pragma unroll
    for (int o = 16; o; o >>= 1) ss += __shfl_xor_sync(0xffffffffu, ss, o);
    if ((threadIdx.x & 31) == 0) red[threadIdx.x >> 5] = ss;
    __syncthreads();
    if (threadIdx.x == 0) {
        float tot = 0.f;
        #pragma unroll
        for (int i = 0; i < 8; i++) tot += red[i];
        s_scale = rsqrtf(tot * (1.f / VALD) + EPSF);
    }
    __syncthreads();
    float sc = s_scale;
    for (int c = threadIdx.x; c < VALD; c += 256) {
        float z = zrow[c];
        float sz = z / (1.f + expf(-z));
        float val = row[c] * sc * (1.f + norm_w[c]) * sz;
        __nv_bfloat16 hv = __float2bfloat16(val);
        ghi[t * VALD + c] = hv;
        glo[t * VALD + c] = __float2bfloat16(val - __bfloat162float(hv));
    }
}

// ---------------- launch ----------------
extern "C" void kernel_launch(void* const* d_in, const int* in_sizes, int n_in,
                              void* d_out, int out_size) {
    const float* x       = (const float*)d_in[0];
    const float* W_qkvz  = (const float*)d_in[1];
    const float* W_ba    = (const float*)d_in[2];
    const float* conv_w  = (const float*)d_in[3];
    const float* dt_bias = (const float*)d_in[4];
    const float* A_log   = (const float*)d_in[5];
    const float* norm_w  = (const float*)d_in[6];
    const float* W_out   = (const float*)d_in[7];
    float* out = (float*)d_out;

    float *p_qkvz, *p_ba, *p_conv, *p_qn, *p_kn, *p_beta, *p_g, *p_core;
    __nv_bfloat16 *p_xhi, *p_xlo, *p_w1hi, *p_w1lo, *p_w2hi, *p_w2lo, *p_ghi, *p_glo;
    cudaGetSymbolAddress((void**)&p_qkvz,  g_qkvz);
    cudaGetSymbolAddress((void**)&p_ba,    g_ba);
    cudaGetSymbolAddress((void**)&p_conv,  g_conv);
    cudaGetSymbolAddress((void**)&p_qn,    g_qn);
    cudaGetSymbolAddress((void**)&p_kn,    g_kn);
    cudaGetSymbolAddress((void**)&p_beta,  g_beta);
    cudaGetSymbolAddress((void**)&p_g,     g_gdec);
    cudaGetSymbolAddress((void**)&p_core,  g_core);
    cudaGetSymbolAddress((void**)&p_xhi,  g_xhi);
    cudaGetSymbolAddress((void**)&p_xlo,  g_xlo);
    cudaGetSymbolAddress((void**)&p_w1hi, g_w1hi);
    cudaGetSymbolAddress((void**)&p_w1lo, g_w1lo);
    cudaGetSymbolAddress((void**)&p_w2hi, g_w2hi);
    cudaGetSymbolAddress((void**)&p_w2lo, g_w2lo);
    cudaGetSymbolAddress((void**)&p_ghi,  g_ghi);
    cudaGetSymbolAddress((void**)&p_glo,  g_glo);

    cudaFuncSetAttribute(gemm_bf16x3, cudaFuncAttributeMaxDynamicSharedMemorySize, GSMEM);

    // splits for GEMM operands
    split_bf16<<<(TOK * (size_t)HID) / 1024, 256>>>(x, p_xhi, p_xlo);
    split_bf16<<<((size_t)PQKVZ * HID) / 1024, 256>>>(W_qkvz, p_w1hi, p_w1lo);
    split_bf16<<<((size_t)HID * VALD) / 1024, 256>>>(W_out, p_w2hi, p_w2lo);

    // 1) qkvz = x @ W_qkvz^T  (mma.sync bf16x3 + ldmatrix)
    gemm_bf16x3<<<dim3(TOK / 128, PQKVZ / 128), 256, GSMEM>>>(
        p_xhi, p_xlo, p_w1hi, p_w1lo, p_qkvz, TOK, PQKVZ, HID);
    // 2) ba = x @ W_ba^T (SIMT, tiny)
    sgemm_nt<<<dim3(1, TOK / BM), 256>>>(x, W_ba, p_ba, TOK, 64, HID);
    // 3) conv + silu
    conv_silu_kernel<<<(TOK * (size_t)CONVD) / 256, 256>>>(p_qkvz, conv_w, p_conv);
    // 4) l2norm + gates
    prep_kernel<<<TOK, 512>>>(p_conv, p_ba, dt_bias, A_log, p_qn, p_kn, p_beta, p_g);
    // 5) delta-rule scan v7 (8 thr/col, 4 warps/SMSP)
    scan_kernel<<<dim3(NV, 2, BATCH), 512>>>(p_qn, p_kn, p_conv, p_beta, p_g, p_core);
    // 6) rmsnorm + gate -> bf16 hi/lo directly
    rmsnorm_gate_kernel<<<TOK, 256>>>(p_core, p_qkvz, norm_w, p_ghi, p_glo);
    // 7) out = gated @ W_out^T (mma.sync bf16x3 + ldmatrix)
    gemm_bf16x3<<<dim3(TOK / 128, HID / 128), 256, GSMEM>>>(
        p_ghi, p_glo, p_w2hi, p_w2lo, out, TOK, HID, VALD);
}

// round 11
// speedup vs baseline: 1.0332x; 1.0332x over previous
#include <cuda_runtime.h>
#include <cuda_bf16.h>
#include <cstdint>

// ---------------- model dims ----------------
#define BATCH 2
#define SEQ   2048
#define TOK   (BATCH*SEQ)        // 4096
#define HID   2048
#define NK    16
#define NV    32
#define DK    128
#define DV    128
#define KEYD  2048               // NK*DK
#define VALD  4096               // NV*DV
#define CONVD 8192               // 2*KEYD + VALD
#define PQKVZ 12288              // 2*KEYD + 2*VALD
#define EPSF  1e-6f

// ---------------- scratch (device globals; no allocation) ----------------
__device__ float g_qkvz [(size_t)TOK * PQKVZ];
__device__ float g_ba   [(size_t)TOK * 64];
__device__ float g_conv [(size_t)TOK * CONVD];
__device__ float g_qn   [(size_t)TOK * KEYD];
__device__ float g_kn   [(size_t)TOK * KEYD];
__device__ float g_beta [(size_t)TOK * NV];
__device__ float g_gdec [(size_t)TOK * NV];
__device__ float g_core [(size_t)TOK * VALD];
// bf16 hi/lo split scratch
__device__ __nv_bfloat16 g_xhi [(size_t)TOK * HID];
__device__ __nv_bfloat16 g_xlo [(size_t)TOK * HID];
__device__ __nv_bfloat16 g_w1hi[(size_t)PQKVZ * HID];
__device__ __nv_bfloat16 g_w1lo[(size_t)PQKVZ * HID];
__device__ __nv_bfloat16 g_w2hi[(size_t)HID * VALD];
__device__ __nv_bfloat16 g_w2lo[(size_t)HID * VALD];
__device__ __nv_bfloat16 g_ghi [(size_t)TOK * VALD];
__device__ __nv_bfloat16 g_glo [(size_t)TOK * VALD];

// ---------------- helpers ----------------
__device__ __forceinline__ uint32_t smem_u32(const void* p) {
    uint32_t r;
    asm("{ .reg .u64 t; cvta.to.shared.u64 t, %1; cvt.u32.u64 %0, t; }" : "=r"(r) : "l"(p));
    return r;
}
__device__ __forceinline__ void cpasync16(uint32_t s, const void* g) {
    asm volatile("cp.async.cg.shared.global [%0], [%1], 16;" :: "r"(s), "l"(g));
}
__device__ __forceinline__ void cpasync4(uint32_t s, const void* g) {
    asm volatile("cp.async.ca.shared.global [%0], [%1], 4;" :: "r"(s), "l"(g));
}
__device__ __forceinline__ void ldmx4(uint32_t* r, uint32_t addr) {
    asm volatile("ldmatrix.sync.aligned.m8n8.x4.shared.b16 {%0,%1,%2,%3}, [%4];"
                 : "=r"(r[0]), "=r"(r[1]), "=r"(r[2]), "=r"(r[3]) : "r"(addr));
}
__device__ __forceinline__ void mma16816(float* c, const uint32_t* a, const uint32_t* b) {
    asm volatile(
        "mma.sync.aligned.m16n8k16.row.col.f32.bf16.bf16.f32 "
        "{%0,%1,%2,%3}, {%4,%5,%6,%7}, {%8,%9}, {%0,%1,%2,%3};"
        : "+f"(c[0]), "+f"(c[1]), "+f"(c[2]), "+f"(c[3])
        : "r"(a[0]), "r"(a[1]), "r"(a[2]), "r"(a[3]), "r"(b[0]), "r"(b[1]));
}
// f32x2 packed math
__device__ __forceinline__ unsigned long long pk2(float a, float b) {
    unsigned long long r; asm("mov.b64 %0, {%1, %2};" : "=l"(r) : "f"(a), "f"(b)); return r;
}
__device__ __forceinline__ unsigned long long fma2(unsigned long long a, unsigned long long b, unsigned long long c) {
    unsigned long long d; asm("fma.rn.f32x2 %0, %1, %2, %3;" : "=l"(d) : "l"(a), "l"(b), "l"(c)); return d;
}
__device__ __forceinline__ unsigned long long mul2(unsigned long long a, unsigned long long b) {
    unsigned long long d; asm("mul.rn.f32x2 %0, %1, %2;" : "=l"(d) : "l"(a), "l"(b)); return d;
}
__device__ __forceinline__ float hadd2(unsigned long long v) {
    float a, b; asm("mov.b64 {%0, %1}, %2;" : "=f"(a), "=f"(b) : "l"(v)); return a + b;
}

// ---------------- split fp32 -> bf16 hi/lo ----------------
__global__ __launch_bounds__(256) void split_bf16(const float* __restrict__ src,
                                                  __nv_bfloat16* __restrict__ hi,
                                                  __nv_bfloat16* __restrict__ lo) {
    size_t i = ((size_t)blockIdx.x * blockDim.x + threadIdx.x) * 4;
    float4 v = *(const float4*)(src + i);
    __nv_bfloat16 h0 = __float2bfloat16(v.x), h1 = __float2bfloat16(v.y);
    __nv_bfloat16 h2 = __float2bfloat16(v.z), h3 = __float2bfloat16(v.w);
    __nv_bfloat16 l0 = __float2bfloat16(v.x - __bfloat162float(h0));
    __nv_bfloat16 l1 = __float2bfloat16(v.y - __bfloat162float(h1));
    __nv_bfloat16 l2 = __float2bfloat16(v.z - __bfloat162float(h2));
    __nv_bfloat16 l3 = __float2bfloat16(v.w - __bfloat162float(h3));
    __nv_bfloat162* hp = (__nv_bfloat162*)(hi + i);
    __nv_bfloat162* lp = (__nv_bfloat162*)(lo + i);
    hp[0] = __nv_bfloat162(h0, h1); hp[1] = __nv_bfloat162(h2, h3);
    lp[0] = __nv_bfloat162(l0, l1); lp[1] = __nv_bfloat162(l2, l3);
}

// ---------------- mma.sync bf16x3 GEMM (NT): C[m,n] = sum_k A[m,k]*B[n,k] ----------------
#define TSTRIDE 80
#define TILE_B  (128 * TSTRIDE)
#define STAGE_B (4 * TILE_B)
#define GSMEM   (2 * STAGE_B)

__global__ __launch_bounds__(256, 2)
void gemm_bf16x3(const __nv_bfloat16* __restrict__ Ah, const __nv_bfloat16* __restrict__ Al,
                 const __nv_bfloat16* __restrict__ Bh, const __nv_bfloat16* __restrict__ Bl,
                 float* __restrict__ C, int M, int N, int K) {
    extern __shared__ char sm[];
    const uint32_t sb = smem_u32(sm);
    const int tid = threadIdx.x;
    const int lane = tid & 31, wid = tid >> 5;
    const int bm = blockIdx.x * 128, bn = blockIdx.y * 128;
    const int wm = (wid & 1) * 64, wn = (wid >> 1) * 32;
    const int grp = lane >> 2, qid = lane & 3;

    const uint32_t a_row = (uint32_t)(lane & 15);
    const uint32_t a_c16 = (uint32_t)((lane >> 4) * 16);
    const uint32_t b_row = (uint32_t)((lane & 7) + ((lane >> 4) & 1) * 8);
    const uint32_t b_c16 = (uint32_t)(((lane >> 3) & 1) * 16);

    float c[4][4][4];
    #pragma unroll
    for (int i = 0; i < 4; i++)
        #pragma unroll
        for (int j = 0; j < 4; j++)
            #pragma unroll
            for (int r = 0; r < 4; r++) c[i][j][r] = 0.f;

    const int niter = K >> 5;

    auto issue = [&](int kblk, int buf) {
        const int k0 = kblk * 32;
        #pragma unroll
        for (int i = 0; i < 2; i++) {
            int chunk = tid + i * 256;
            int row = chunk >> 2, c16 = chunk & 3;
            size_t ga = (size_t)(bm + row) * K + k0 + c16 * 8;
            size_t gb = (size_t)(bn + row) * K + k0 + c16 * 8;
            uint32_t so = sb + buf * STAGE_B + row * TSTRIDE + c16 * 16;
            cpasync16(so,              Ah + ga);
            cpasync16(so + TILE_B,     Al + ga);
            cpasync16(so + 2 * TILE_B, Bh + gb);
            cpasync16(so + 3 * TILE_B, Bl + gb);
        }
    };

    issue(0, 0);
    asm volatile("cp.async.commit_group;" ::: "memory");
    issue(1, 1);
    asm volatile("cp.async.commit_group;" ::: "memory");

    for (int it = 0; it < niter; it++) {
        asm volatile("cp.async.wait_group 1;" ::: "memory");
        __syncthreads();
        const int buf = it & 1;
        const uint32_t base = sb + buf * STAGE_B;

        #pragma unroll
        for (int ks = 0; ks < 2; ks++) {
            const uint32_t koff = ks * 32;
            const uint32_t abase = base + (uint32_t)(wm + a_row) * TSTRIDE + koff + a_c16;
            const uint32_t bbase = base + 2 * TILE_B + (uint32_t)(wn + b_row) * TSTRIDE + koff + b_c16;
            uint32_t ah[4][4], bh[2][4];
            #pragma unroll
            for (int i = 0; i < 4; i++) ldmx4(ah[i], abase + (uint32_t)(i * 16) * TSTRIDE);
            #pragma unroll
            for (int J = 0; J < 2; J++) ldmx4(bh[J], bbase + (uint32_t)(J * 16) * TSTRIDE);
            // phase 1: hh
            #pragma unroll
            for (int i = 0; i < 4; i++)
                #pragma unroll
                for (int j = 0; j < 4; j++) mma16816(c[i][j], ah[i], &bh[j >> 1][(j & 1) * 2]);
            // phase 2: lh
            {
                uint32_t al[4][4];
                #pragma unroll
                for (int i = 0; i < 4; i++) ldmx4(al[i], abase + TILE_B + (uint32_t)(i * 16) * TSTRIDE);
                #pragma unroll
                for (int i = 0; i < 4; i++)
                    #pragma unroll
                    for (int j = 0; j < 4; j++) mma16816(c[i][j], al[i], &bh[j >> 1][(j & 1) * 2]);
            }
            // phase 3: hl
            {
                uint32_t bl[2][4];
                #pragma unroll
                for (int J = 0; J < 2; J++) ldmx4(bl[J], bbase + TILE_B + (uint32_t)(J * 16) * TSTRIDE);
                #pragma unroll
                for (int i = 0; i < 4; i++)
                    #pragma unroll
                    for (int j = 0; j < 4; j++) mma16816(c[i][j], ah[i], &bl[j >> 1][(j & 1) * 2]);
            }
        }
        __syncthreads();
        if (it + 2 < niter) issue(it + 2, buf);
        asm volatile("cp.async.commit_group;" ::: "memory");
    }

    #pragma unroll
    for (int i = 0; i < 4; i++) {
        const int row0 = bm + wm + i * 16 + grp;
        #pragma unroll
        for (int j = 0; j < 4; j++) {
            const int col = bn + wn + j * 8 + qid * 2;
            float2 v01 = make_float2(c[i][j][0], c[i][j][1]);
            float2 v23 = make_float2(c[i][j][2], c[i][j][3]);
            *(float2*)(C + (size_t)row0 * N + col)       = v01;
            *(float2*)(C + (size_t)(row0 + 8) * N + col) = v23;
        }
    }
}

// ---------------- SIMT SGEMM (NT) for tiny ba GEMM ----------------
#define BM 128
#define BN 128
#define BKK 16
__global__ __launch_bounds__(256) void sgemm_nt(const float* __restrict__ A,
                                                const float* __restrict__ B,
                                                float* __restrict__ C,
                                                int M, int N, int K) {
    __shared__ float As[BKK][BM];
    __shared__ float Bs[BKK][BN];
    const int tid = threadIdx.x;
    const int bm = blockIdx.y * BM;
    const int bn = blockIdx.x * BN;
    const int tx = tid & 15;
    const int ty = tid >> 4;
    const int lrow = tid >> 2;
    const int lk4 = (tid & 3) * 4;

    float acc[8][8];
    #pragma unroll
    for (int i = 0; i < 8; i++)
        #pragma unroll
        for (int j = 0; j < 8; j++) acc[i][j] = 0.f;

    for (int k0 = 0; k0 < K; k0 += BKK) {
        #pragma unroll
        for (int it = 0; it < 2; it++) {
            int row = lrow + it * 64;
            float4 v = *(const float4*)(A + (size_t)(bm + row) * K + k0 + lk4);
            As[lk4 + 0][row] = v.x; As[lk4 + 1][row] = v.y;
            As[lk4 + 2][row] = v.z; As[lk4 + 3][row] = v.w;
        }
        #pragma unroll
        for (int it = 0; it < 2; it++) {
            int row = lrow + it * 64;
            int gn = bn + row;
            float4 v = make_float4(0.f, 0.f, 0.f, 0.f);
            if (gn < N) v = *(const float4*)(B + (size_t)gn * K + k0 + lk4);
            Bs[lk4 + 0][row] = v.x; Bs[lk4 + 1][row] = v.y;
            Bs[lk4 + 2][row] = v.z; Bs[lk4 + 3][row] = v.w;
        }
        __syncthreads();
        #pragma unroll
        for (int kk = 0; kk < BKK; kk++) {
            float ar[8], br[8];
            #pragma unroll
            for (int i = 0; i < 8; i++) ar[i] = As[kk][ty * 8 + i];
            #pragma unroll
            for (int j = 0; j < 8; j++) br[j] = Bs[kk][tx * 8 + j];
            #pragma unroll
            for (int i = 0; i < 8; i++)
                #pragma unroll
                for (int j = 0; j < 8; j++)
                    acc[i][j] = fmaf(ar[i], br[j], acc[i][j]);
        }
        __syncthreads();
    }
    #pragma unroll
    for (int i = 0; i < 8; i++) {
        int gm = bm + ty * 8 + i;
        #pragma unroll
        for (int j = 0; j < 8; j++) {
            int gn = bn + tx * 8 + j;
            if (gn < N) C[(size_t)gm * N + gn] = acc[i][j];
        }
    }
}

// ---------------- depthwise causal conv1d (K=4) + SiLU ----------------
__global__ void conv_silu_kernel(const float* __restrict__ qkvz,
                                 const float* __restrict__ cw,
                                 float* __restrict__ out) {
    size_t idx = (size_t)blockIdx.x * blockDim.x + threadIdx.x;
    int c = (int)(idx & (CONVD - 1));
    size_t t = idx >> 13;
    int s = (int)(t & (SEQ - 1));
    size_t b = t >> 11;
    const float* base = qkvz + (b * SEQ) * (size_t)PQKVZ + c;
    float w0 = cw[c * 4 + 0], w1 = cw[c * 4 + 1], w2 = cw[c * 4 + 2], w3 = cw[c * 4 + 3];
    float acc = w3 * base[(size_t)s * PQKVZ];
    if (s >= 1) acc = fmaf(w2, base[(size_t)(s - 1) * PQKVZ], acc);
    if (s >= 2) acc = fmaf(w1, base[(size_t)(s - 2) * PQKVZ], acc);
    if (s >= 3) acc = fmaf(w0, base[(size_t)(s - 3) * PQKVZ], acc);
    out[idx] = acc / (1.f + expf(-acc));
}

// ---------------- l2norm(q,k) + gates ----------------
__global__ __launch_bounds__(512) void prep_kernel(const float* __restrict__ conv,
                                                   const float* __restrict__ ba,
                                                   const float* __restrict__ dt_bias,
                                                   const float* __restrict__ A_log,
                                                   float* __restrict__ qn,
                                                   float* __restrict__ kn,
                                                   float* __restrict__ beta,
                                                   float* __restrict__ gdec) {
    size_t t = blockIdx.x;
    int w = threadIdx.x >> 5;
    int l = threadIdx.x & 31;
    const float* cq = conv + t * CONVD + w * DK;
    const float* ck = conv + t * CONVD + KEYD + w * DK;
    float qv[4], kv[4];
    float sq = 0.f, sk = 0.f;
    #pragma unroll
    for (int i = 0; i < 4; i++) {
        qv[i] = cq[l + 32 * i]; sq = fmaf(qv[i], qv[i], sq);
        kv[i] = ck[l + 32 * i]; sk = fmaf(kv[i], kv[i], sk);
    }
    #pragma unroll
    for (int o = 16; o; o >>= 1) {
        sq += __shfl_xor_sync(0xffffffffu, sq, o);
        sk += __shfl_xor_sync(0xffffffffu, sk, o);
    }
    float rq = rsqrtf(sq + EPSF), rk = rsqrtf(sk + EPSF);
    #pragma unroll
    for (int i = 0; i < 4; i++) {
        qn[(t * NK + w) * DK + l + 32 * i] = qv[i] * rq;
        kn[(t * NK + w) * DK + l + 32 * i] = kv[i] * rk;
    }
    if (threadIdx.x < NV) {
        int h = threadIdx.x;
        float bv = ba[t * 64 + h];
        float av = ba[t * 64 + NV + h];
        beta[t * NV + h] = 1.f / (1.f + expf(-bv));
        float xx = av + dt_bias[h];
        float sp = (xx > 20.f) ? xx : log1pf(expf(xx));
        gdec[t * NV + h] = expf(-expf(A_log[h]) * sp);
    }
}

// ---------------- gated delta-rule scan v8: v5 + k cached in registers ----------------
// Grid (NV, 2, BATCH) = 128 CTAs; 256 threads: 4 per DV column (DK quarters of 32).
// k fragments loaded ONCE per step into registers, reused in the update loop
// (removes 1/3 of the per-step LDS.128 traffic — the measured bottleneck).
#define SCH   8
#define KROW  144   // 4 quarters * 36 floats
__global__ __launch_bounds__(256) void scan_kernel(const float* __restrict__ qn,
                                                   const float* __restrict__ kn,
                                                   const float* __restrict__ conv,
                                                   const float* __restrict__ beta,
                                                   const float* __restrict__ gdec,
                                                   float* __restrict__ core) {
    const int h = blockIdx.x;        // value head
    const int dv0 = blockIdx.y * 64; // DV half
    const int b = blockIdx.z;
    const int nk = h >> 1;
    const int tid = threadIdx.x;
    const int col = tid >> 2;        // local DV col 0..63
    const int quarter = tid & 3;     // DK quarter
    __shared__ float ksm[2][SCH][KROW];
    __shared__ float qsm[2][SCH][KROW];
    __shared__ float vsm[2][SCH][64];
    __shared__ float gsm[2][SCH], bsm[2][SCH];

    unsigned long long st[16];       // 32 floats of state (this quarter x this col)
    #pragma unroll
    for (int j = 0; j < 16; j++) st[j] = 0ull;

    const size_t tbase = (size_t)b * SEQ;
    const int krow_t = tid >> 5, kln = tid & 31;
    const int kqoff = (kln >> 3) * 36 + (kln & 7) * 4;   // quarter-padded dst offset

    auto issue = [&](int blk, int buf) {
        const size_t t0 = tbase + (size_t)blk * SCH;
        cpasync16(smem_u32(&ksm[buf][krow_t][kqoff]), kn + ((t0 + krow_t) * NK + nk) * DK + kln * 4);
        cpasync16(smem_u32(&qsm[buf][krow_t][kqoff]), qn + ((t0 + krow_t) * NK + nk) * DK + kln * 4);
        if (tid < 128) {
            int vr = tid >> 4, vc = (tid & 15) * 4;
            cpasync16(smem_u32(&vsm[buf][vr][vc]),
                      conv + (t0 + vr) * CONVD + 2 * KEYD + h * DV + dv0 + vc);
        } else if (tid < 128 + SCH) {
            cpasync4(smem_u32(&gsm[buf][tid - 128]), gdec + (t0 + tid - 128) * NV + h);
        } else if (tid < 128 + 2 * SCH) {
            cpasync4(smem_u32(&bsm[buf][tid - 128 - SCH]), beta + (t0 + tid - 128 - SCH) * NV + h);
        }
    };

    issue(0, 0);
    asm volatile("cp.async.commit_group;" ::: "memory");
    issue(1, 1);
    asm volatile("cp.async.commit_group;" ::: "memory");

    const int nblk = SEQ / SCH;
    for (int blk = 0; blk < nblk; blk++) {
        const int buf = blk & 1;
        asm volatile("cp.async.wait_group 1;" ::: "memory");
        __syncthreads();

        #pragma unroll
        for (int i = 0; i < SCH; i++) {
            const ulonglong2* kk = (const ulonglong2*)&ksm[buf][i][quarter * 36];
            const ulonglong2* qq = (const ulonglong2*)&qsm[buf][i][quarter * 36];
            float vt = vsm[buf][i][col];
            float ge = gsm[buf][i];
            float bt = bsm[buf][i];

            // kvd = k . state ; cache k fragments in registers for reuse below
            ulonglong2 kreg[8];
            unsigned long long a0 = 0ull, a1 = 0ull, a2 = 0ull, a3 = 0ull;
            #pragma unroll
            for (int j = 0; j < 8; j += 2) {
                kreg[j] = kk[j]; kreg[j + 1] = kk[j + 1];
                a0 = fma2(kreg[j].x,     st[2 * j + 0], a0);
                a1 = fma2(kreg[j].y,     st[2 * j + 1], a1);
                a2 = fma2(kreg[j + 1].x, st[2 * j + 2], a2);
                a3 = fma2(kreg[j + 1].y, st[2 * j + 3], a3);
            }
            float kvd = (hadd2(a0) + hadd2(a1)) + (hadd2(a2) + hadd2(a3));
            kvd += __shfl_xor_sync(0xffffffffu, kvd, 1);
            kvd += __shfl_xor_sync(0xffffffffu, kvd, 2);
            float delta = bt * (vt - ge * kvd);
            unsigned long long ge2 = pk2(ge, ge);
            unsigned long long d2 = pk2(delta, delta);

            unsigned long long o0 = 0ull, o1 = 0ull;
            #pragma unroll
            for (int j = 0; j < 8; j++) {
                ulonglong2 kj = kreg[j], qj = qq[j];
                st[2 * j + 0] = fma2(ge2, st[2 * j + 0], mul2(kj.x, d2));
                o0 = fma2(qj.x, st[2 * j + 0], o0);
                st[2 * j + 1] = fma2(ge2, st[2 * j + 1], mul2(kj.y, d2));
                o1 = fma2(qj.y, st[2 * j + 1], o1);
            }
            float o = hadd2(o0) + hadd2(o1);
            o += __shfl_xor_sync(0xffffffffu, o, 1);
            o += __shfl_xor_sync(0xffffffffu, o, 2);
            if (quarter == 0)
                core[(tbase + (size_t)blk * SCH + i) * VALD + h * DV + dv0 + col] = o;
        }

        __syncthreads();
        if (blk + 2 < nblk) issue(blk + 2, buf);
        asm volatile("cp.async.commit_group;" ::: "memory");
    }
}

// ---------------- RMSNorm(1+w) + silu(z) gate -> bf16 hi/lo ----------------
__global__ __launch_bounds__(256) void rmsnorm_gate_kernel(const float* __restrict__ core,
                                                           const float* __restrict__ qkvz,
                                                           const float* __restrict__ norm_w,
                                                           __nv_bfloat16* __restrict__ ghi,
                                                           __nv_bfloat16* __restrict__ glo) {
    size_t t = blockIdx.x;
    __shared__ float red[8];
    __shared__ float s_scale;
    const float* row = core + t * VALD;
    const float* zrow = qkvz + t * PQKVZ + 2 * KEYD + VALD;
    float ss = 0.f;
    for (int c = threadIdx.x; c < VALD; c += 256) { float v = row[c]; ss = fmaf(v, v, ss); }
    #pragma unroll
    for (int o = 16; o; o >>= 1) ss += __shfl_xor_sync(0xffffffffu, ss, o);
    if ((threadIdx.x & 31) == 0) red[threadIdx.x >> 5] = ss;
    __syncthreads();
    if (threadIdx.x == 0) {
        float tot = 0.f;
        #pragma unroll
        for (int i = 0; i < 8; i++) tot += red[i];
        s_scale = rsqrtf(tot * (1.f / VALD) + EPSF);
    }
    __syncthreads();
    float sc = s_scale;
    for (int c = threadIdx.x; c < VALD; c += 256) {
        float z = zrow[c];
        float sz = z / (1.f + expf(-z));
        float val = row[c] * sc * (1.f + norm_w[c]) * sz;
        __nv_bfloat16 hv = __float2bfloat16(val);
        ghi[t * VALD + c] = hv;
        glo[t * VALD + c] = __float2bfloat16(val - __bfloat162float(hv));
    }
}

// ---------------- launch ----------------
extern "C" void kernel_launch(void* const* d_in, const int* in_sizes, int n_in,
                              void* d_out, int out_size) {
    const float* x       = (const float*)d_in[0];
    const float* W_qkvz  = (const float*)d_in[1];
    const float* W_ba    = (const float*)d_in[2];
    const float* conv_w  = (const float*)d_in[3];
    const float* dt_bias = (const float*)d_in[4];
    const float* A_log   = (const float*)d_in[5];
    const float* norm_w  = (const float*)d_in[6];
    const float* W_out   = (const float*)d_in[7];
    float* out = (float*)d_out;

    float *p_qkvz, *p_ba, *p_conv, *p_qn, *p_kn, *p_beta, *p_g, *p_core;
    __nv_bfloat16 *p_xhi, *p_xlo, *p_w1hi, *p_w1lo, *p_w2hi, *p_w2lo, *p_ghi, *p_glo;
    cudaGetSymbolAddress((void**)&p_qkvz,  g_qkvz);
    cudaGetSymbolAddress((void**)&p_ba,    g_ba);
    cudaGetSymbolAddress((void**)&p_conv,  g_conv);
    cudaGetSymbolAddress((void**)&p_qn,    g_qn);
    cudaGetSymbolAddress((void**)&p_kn,    g_kn);
    cudaGetSymbolAddress((void**)&p_beta,  g_beta);
    cudaGetSymbolAddress((void**)&p_g,     g_gdec);
    cudaGetSymbolAddress((void**)&p_core,  g_core);
    cudaGetSymbolAddress((void**)&p_xhi,  g_xhi);
    cudaGetSymbolAddress((void**)&p_xlo,  g_xlo);
    cudaGetSymbolAddress((void**)&p_w1hi, g_w1hi);
    cudaGetSymbolAddress((void**)&p_w1lo, g_w1lo);
    cudaGetSymbolAddress((void**)&p_w2hi, g_w2hi);
    cudaGetSymbolAddress((void**)&p_w2lo, g_w2lo);
    cudaGetSymbolAddress((void**)&p_ghi,  g_ghi);
    cudaGetSymbolAddress((void**)&p_glo,  g_glo);

    cudaFuncSetAttribute(gemm_bf16x3, cudaFuncAttributeMaxDynamicSharedMemorySize, GSMEM);

    // splits for GEMM operands
    split_bf16<<<(TOK * (size_t)HID) / 1024, 256>>>(x, p_xhi, p_xlo);
    split_bf16<<<((size_t)PQKVZ * HID) / 1024, 256>>>(W_qkvz, p_w1hi, p_w1lo);
    split_bf16<<<((size_t)HID * VALD) / 1024, 256>>>(W_out, p_w2hi, p_w2lo);

    // 1) qkvz = x @ W_qkvz^T  (mma.sync bf16x3 + ldmatrix)
    gemm_bf16x3<<<dim3(TOK / 128, PQKVZ / 128), 256, GSMEM>>>(
        p_xhi, p_xlo, p_w1hi, p_w1lo, p_qkvz, TOK, PQKVZ, HID);
    // 2) ba = x @ W_ba^T (SIMT, tiny)
    sgemm_nt<<<dim3(1, TOK / BM), 256>>>(x, W_ba, p_ba, TOK, 64, HID);
    // 3) conv + silu
    conv_silu_kernel<<<(TOK * (size_t)CONVD) / 256, 256>>>(p_qkvz, conv_w, p_conv);
    // 4) l2norm + gates
    prep_kernel<<<TOK, 512>>>(p_conv, p_ba, dt_bias, A_log, p_qn, p_kn, p_beta, p_g);
    // 5) delta-rule scan v8 (v5 + register-cached k)
    scan_kernel<<<dim3(NV, 2, BATCH), 256>>>(p_qn, p_kn, p_conv, p_beta, p_g, p_core);
    // 6) rmsnorm + gate -> bf16 hi/lo directly
    rmsnorm_gate_kernel<<<TOK, 256>>>(p_core, p_qkvz, norm_w, p_ghi, p_glo);
    // 7) out = gated @ W_out^T (mma.sync bf16x3 + ldmatrix)
    gemm_bf16x3<<<dim3(TOK / 128, HID / 128), 256, GSMEM>>>(
        p_ghi, p_glo, p_w2hi, p_w2lo, out, TOK, HID, VALD);
}

// round 12
// speedup vs baseline: 1.0529x; 1.0191x over previous
#include <cuda_runtime.h>
#include <cuda_bf16.h>
#include <cstdint>

// ---------------- model dims ----------------
#define BATCH 2
#define SEQ   2048
#define TOK   (BATCH*SEQ)        // 4096
#define HID   2048
#define NK    16
#define NV    32
#define DK    128
#define DV    128
#define KEYD  2048               // NK*DK
#define VALD  4096               // NV*DV
#define CONVD 8192               // 2*KEYD + VALD
#define PQKVZ 12288              // 2*KEYD + 2*VALD
#define EPSF  1e-6f

// ---------------- scratch (device globals; no allocation) ----------------
__device__ float g_qkvz [(size_t)TOK * PQKVZ];
__device__ float g_ba   [(size_t)TOK * 64];
__device__ float g_conv [(size_t)TOK * CONVD];
__device__ float g_qn   [(size_t)TOK * KEYD];
__device__ float g_kn   [(size_t)TOK * KEYD];
__device__ float g_beta [(size_t)TOK * NV];
__device__ float g_gdec [(size_t)TOK * NV];
__device__ float g_core [(size_t)TOK * VALD];
// bf16 hi/lo split scratch
__device__ __nv_bfloat16 g_xhi [(size_t)TOK * HID];
__device__ __nv_bfloat16 g_xlo [(size_t)TOK * HID];
__device__ __nv_bfloat16 g_w1hi[(size_t)PQKVZ * HID];
__device__ __nv_bfloat16 g_w1lo[(size_t)PQKVZ * HID];
__device__ __nv_bfloat16 g_w2hi[(size_t)HID * VALD];
__device__ __nv_bfloat16 g_w2lo[(size_t)HID * VALD];
__device__ __nv_bfloat16 g_ghi [(size_t)TOK * VALD];
__device__ __nv_bfloat16 g_glo [(size_t)TOK * VALD];

// ---------------- helpers ----------------
__device__ __forceinline__ uint32_t smem_u32(const void* p) {
    uint32_t r;
    asm("{ .reg .u64 t; cvta.to.shared.u64 t, %1; cvt.u32.u64 %0, t; }" : "=r"(r) : "l"(p));
    return r;
}
__device__ __forceinline__ void cpasync16(uint32_t s, const void* g) {
    asm volatile("cp.async.cg.shared.global [%0], [%1], 16;" :: "r"(s), "l"(g));
}
__device__ __forceinline__ void cpasync4(uint32_t s, const void* g) {
    asm volatile("cp.async.ca.shared.global [%0], [%1], 4;" :: "r"(s), "l"(g));
}
__device__ __forceinline__ void ldmx4(uint32_t* r, uint32_t addr) {
    asm volatile("ldmatrix.sync.aligned.m8n8.x4.shared.b16 {%0,%1,%2,%3}, [%4];"
                 : "=r"(r[0]), "=r"(r[1]), "=r"(r[2]), "=r"(r[3]) : "r"(addr));
}
__device__ __forceinline__ void mma16816(float* c, const uint32_t* a, const uint32_t* b) {
    asm volatile(
        "mma.sync.aligned.m16n8k16.row.col.f32.bf16.bf16.f32 "
        "{%0,%1,%2,%3}, {%4,%5,%6,%7}, {%8,%9}, {%0,%1,%2,%3};"
        : "+f"(c[0]), "+f"(c[1]), "+f"(c[2]), "+f"(c[3])
        : "r"(a[0]), "r"(a[1]), "r"(a[2]), "r"(a[3]), "r"(b[0]), "r"(b[1]));
}
// f32x2 packed math
__device__ __forceinline__ unsigned long long pk2(float a, float b) {
    unsigned long long r; asm("mov.b64 %0, {%1, %2};" : "=l"(r) : "f"(a), "f"(b)); return r;
}
__device__ __forceinline__ unsigned long long fma2(unsigned long long a, unsigned long long b, unsigned long long c) {
    unsigned long long d; asm("fma.rn.f32x2 %0, %1, %2, %3;" : "=l"(d) : "l"(a), "l"(b), "l"(c)); return d;
}
__device__ __forceinline__ unsigned long long mul2(unsigned long long a, unsigned long long b) {
    unsigned long long d; asm("mul.rn.f32x2 %0, %1, %2;" : "=l"(d) : "l"(a), "l"(b)); return d;
}
__device__ __forceinline__ float hadd2(unsigned long long v) {
    float a, b; asm("mov.b64 {%0, %1}, %2;" : "=f"(a), "=f"(b) : "l"(v)); return a + b;
}
// named barriers (warp-aligned thread groups)
#define NBAR(id, cnt) asm volatile("bar.sync %0, %1;" :: "r"(id), "r"(cnt) : "memory")

// ---------------- split fp32 -> bf16 hi/lo ----------------
__global__ __launch_bounds__(256) void split_bf16(const float* __restrict__ src,
                                                  __nv_bfloat16* __restrict__ hi,
                                                  __nv_bfloat16* __restrict__ lo) {
    size_t i = ((size_t)blockIdx.x * blockDim.x + threadIdx.x) * 4;
    float4 v = *(const float4*)(src + i);
    __nv_bfloat16 h0 = __float2bfloat16(v.x), h1 = __float2bfloat16(v.y);
    __nv_bfloat16 h2 = __float2bfloat16(v.z), h3 = __float2bfloat16(v.w);
    __nv_bfloat16 l0 = __float2bfloat16(v.x - __bfloat162float(h0));
    __nv_bfloat16 l1 = __float2bfloat16(v.y - __bfloat162float(h1));
    __nv_bfloat16 l2 = __float2bfloat16(v.z - __bfloat162float(h2));
    __nv_bfloat16 l3 = __float2bfloat16(v.w - __bfloat162float(h3));
    __nv_bfloat162* hp = (__nv_bfloat162*)(hi + i);
    __nv_bfloat162* lp = (__nv_bfloat162*)(lo + i);
    hp[0] = __nv_bfloat162(h0, h1); hp[1] = __nv_bfloat162(h2, h3);
    lp[0] = __nv_bfloat162(l0, l1); lp[1] = __nv_bfloat162(l2, l3);
}

// ---------------- mma.sync bf16x3 GEMM (NT): C[m,n(ldc)] = sum_k A[m,k]*B[n,k] ----------------
#define TSTRIDE 80
#define TILE_B  (128 * TSTRIDE)
#define STAGE_B (4 * TILE_B)
#define GSMEM   (2 * STAGE_B)

__global__ __launch_bounds__(256, 2)
void gemm_bf16x3(const __nv_bfloat16* __restrict__ Ah, const __nv_bfloat16* __restrict__ Al,
                 const __nv_bfloat16* __restrict__ Bh, const __nv_bfloat16* __restrict__ Bl,
                 float* __restrict__ C, int M, int N, int K, int ldc) {
    extern __shared__ __align__(16) char sm[];
    const uint32_t sb = smem_u32(sm);
    const int tid = threadIdx.x;
    const int lane = tid & 31, wid = tid >> 5;
    const int bm = blockIdx.x * 128, bn = blockIdx.y * 128;
    const int wm = (wid & 1) * 64, wn = (wid >> 1) * 32;
    const int grp = lane >> 2, qid = lane & 3;

    const uint32_t a_row = (uint32_t)(lane & 15);
    const uint32_t a_c16 = (uint32_t)((lane >> 4) * 16);
    const uint32_t b_row = (uint32_t)((lane & 7) + ((lane >> 4) & 1) * 8);
    const uint32_t b_c16 = (uint32_t)(((lane >> 3) & 1) * 16);

    float c[4][4][4];
    #pragma unroll
    for (int i = 0; i < 4; i++)
        #pragma unroll
        for (int j = 0; j < 4; j++)
            #pragma unroll
            for (int r = 0; r < 4; r++) c[i][j][r] = 0.f;

    const int niter = K >> 5;

    auto issue = [&](int kblk, int buf) {
        const int k0 = kblk * 32;
        #pragma unroll
        for (int i = 0; i < 2; i++) {
            int chunk = tid + i * 256;
            int row = chunk >> 2, c16 = chunk & 3;
            size_t ga = (size_t)(bm + row) * K + k0 + c16 * 8;
            size_t gb = (size_t)(bn + row) * K + k0 + c16 * 8;
            uint32_t so = sb + buf * STAGE_B + row * TSTRIDE + c16 * 16;
            cpasync16(so,              Ah + ga);
            cpasync16(so + TILE_B,     Al + ga);
            cpasync16(so + 2 * TILE_B, Bh + gb);
            cpasync16(so + 3 * TILE_B, Bl + gb);
        }
    };

    issue(0, 0);
    asm volatile("cp.async.commit_group;" ::: "memory");
    issue(1, 1);
    asm volatile("cp.async.commit_group;" ::: "memory");

    for (int it = 0; it < niter; it++) {
        asm volatile("cp.async.wait_group 1;" ::: "memory");
        __syncthreads();
        const int buf = it & 1;
        const uint32_t base = sb + buf * STAGE_B;

        #pragma unroll
        for (int ks = 0; ks < 2; ks++) {
            const uint32_t koff = ks * 32;
            const uint32_t abase = base + (uint32_t)(wm + a_row) * TSTRIDE + koff + a_c16;
            const uint32_t bbase = base + 2 * TILE_B + (uint32_t)(wn + b_row) * TSTRIDE + koff + b_c16;
            uint32_t ah[4][4], bh[2][4];
            #pragma unroll
            for (int i = 0; i < 4; i++) ldmx4(ah[i], abase + (uint32_t)(i * 16) * TSTRIDE);
            #pragma unroll
            for (int J = 0; J < 2; J++) ldmx4(bh[J], bbase + (uint32_t)(J * 16) * TSTRIDE);
            #pragma unroll
            for (int i = 0; i < 4; i++)
                #pragma unroll
                for (int j = 0; j < 4; j++) mma16816(c[i][j], ah[i], &bh[j >> 1][(j & 1) * 2]);
            {
                uint32_t al[4][4];
                #pragma unroll
                for (int i = 0; i < 4; i++) ldmx4(al[i], abase + TILE_B + (uint32_t)(i * 16) * TSTRIDE);
                #pragma unroll
                for (int i = 0; i < 4; i++)
                    #pragma unroll
                    for (int j = 0; j < 4; j++) mma16816(c[i][j], al[i], &bh[j >> 1][(j & 1) * 2]);
            }
            {
                uint32_t bl[2][4];
                #pragma unroll
                for (int J = 0; J < 2; J++) ldmx4(bl[J], bbase + TILE_B + (uint32_t)(J * 16) * TSTRIDE);
                #pragma unroll
                for (int i = 0; i < 4; i++)
                    #pragma unroll
                    for (int j = 0; j < 4; j++) mma16816(c[i][j], ah[i], &bl[j >> 1][(j & 1) * 2]);
            }
        }
        __syncthreads();
        if (it + 2 < niter) issue(it + 2, buf);
        asm volatile("cp.async.commit_group;" ::: "memory");
    }

    #pragma unroll
    for (int i = 0; i < 4; i++) {
        const int row0 = bm + wm + i * 16 + grp;
        #pragma unroll
        for (int j = 0; j < 4; j++) {
            const int col = bn + wn + j * 8 + qid * 2;
            float2 v01 = make_float2(c[i][j][0], c[i][j][1]);
            float2 v23 = make_float2(c[i][j][2], c[i][j][3]);
            *(float2*)(C + (size_t)row0 * ldc + col)       = v01;
            *(float2*)(C + (size_t)(row0 + 8) * ldc + col) = v23;
        }
    }
}

// ---------------- fused scan + z-GEMM (warp-specialized) ----------------
// grid 144, 512 threads. Threads 0..255 (cid<128): delta-rule scan v5 (NBAR 1).
// Threads 256..511: z-GEMM tiles (qkvz cols 8192..12287), NBAR 2, dynamic smem.
#define SCH   8
#define KROW  144   // 4 quarters * 36 floats
#define ZTILES 1024 // 32 (M) x 32 (N)

__global__ __launch_bounds__(512)
void scan_zgemm(const float* __restrict__ qn, const float* __restrict__ kn,
                const float* __restrict__ conv, const float* __restrict__ beta,
                const float* __restrict__ gdec, float* __restrict__ core,
                const __nv_bfloat16* __restrict__ Ah, const __nv_bfloat16* __restrict__ Al,
                const __nv_bfloat16* __restrict__ Bh, const __nv_bfloat16* __restrict__ Bl,
                float* __restrict__ qkvz) {
    extern __shared__ __align__(16) char dynsm[];        // 81920 B for gemm
    __shared__ float ksm[2][SCH][KROW];
    __shared__ float qsm[2][SCH][KROW];
    __shared__ float vsm[2][SCH][64];
    __shared__ float gsm[2][SCH], bsm[2][SCH];

    const int cid = blockIdx.x;
    const int tid = threadIdx.x;

    if (tid < 256) {
        // ===================== SCAN half (cid < 128) =====================
        if (cid >= 128) return;
        const int h   = cid & 31;
        const int dv0 = ((cid >> 5) & 1) * 64;
        const int b   = cid >> 6;
        const int nk = h >> 1;
        const int col = tid >> 2;
        const int quarter = tid & 3;

        unsigned long long st[16];
        #pragma unroll
        for (int j = 0; j < 16; j++) st[j] = 0ull;

        const size_t tbase = (size_t)b * SEQ;
        const int krow_t = tid >> 5, kln = tid & 31;
        const int kqoff = (kln >> 3) * 36 + (kln & 7) * 4;

        auto issue = [&](int blk, int buf) {
            const size_t t0 = tbase + (size_t)blk * SCH;
            cpasync16(smem_u32(&ksm[buf][krow_t][kqoff]), kn + ((t0 + krow_t) * NK + nk) * DK + kln * 4);
            cpasync16(smem_u32(&qsm[buf][krow_t][kqoff]), qn + ((t0 + krow_t) * NK + nk) * DK + kln * 4);
            if (tid < 128) {
                int vr = tid >> 4, vc = (tid & 15) * 4;
                cpasync16(smem_u32(&vsm[buf][vr][vc]),
                          conv + (t0 + vr) * CONVD + 2 * KEYD + h * DV + dv0 + vc);
            } else if (tid < 128 + SCH) {
                cpasync4(smem_u32(&gsm[buf][tid - 128]), gdec + (t0 + tid - 128) * NV + h);
            } else if (tid < 128 + 2 * SCH) {
                cpasync4(smem_u32(&bsm[buf][tid - 128 - SCH]), beta + (t0 + tid - 128 - SCH) * NV + h);
            }
        };

        issue(0, 0);
        asm volatile("cp.async.commit_group;" ::: "memory");
        issue(1, 1);
        asm volatile("cp.async.commit_group;" ::: "memory");

        const int nblk = SEQ / SCH;
        for (int blk = 0; blk < nblk; blk++) {
            const int buf = blk & 1;
            asm volatile("cp.async.wait_group 1;" ::: "memory");
            NBAR(1, 256);

            #pragma unroll
            for (int i = 0; i < SCH; i++) {
                const ulonglong2* kk = (const ulonglong2*)&ksm[buf][i][quarter * 36];
                const ulonglong2* qq = (const ulonglong2*)&qsm[buf][i][quarter * 36];
                float vt = vsm[buf][i][col];
                float ge = gsm[buf][i];
                float bt = bsm[buf][i];

                unsigned long long a0 = 0ull, a1 = 0ull;
                #pragma unroll
                for (int j = 0; j < 8; j++) {
                    ulonglong2 kj = kk[j];
                    a0 = fma2(kj.x, st[2 * j + 0], a0);
                    a1 = fma2(kj.y, st[2 * j + 1], a1);
                }
                float kvd = hadd2(a0) + hadd2(a1);
                kvd += __shfl_xor_sync(0xffffffffu, kvd, 1);
                kvd += __shfl_xor_sync(0xffffffffu, kvd, 2);
                float delta = bt * (vt - ge * kvd);
                unsigned long long ge2 = pk2(ge, ge);
                unsigned long long d2 = pk2(delta, delta);

                unsigned long long o0 = 0ull, o1 = 0ull;
                #pragma unroll
                for (int j = 0; j < 8; j++) {
                    ulonglong2 kj = kk[j], qj = qq[j];
                    st[2 * j + 0] = fma2(ge2, st[2 * j + 0], mul2(kj.x, d2));
                    o0 = fma2(qj.x, st[2 * j + 0], o0);
                    st[2 * j + 1] = fma2(ge2, st[2 * j + 1], mul2(kj.y, d2));
                    o1 = fma2(qj.y, st[2 * j + 1], o1);
                }
                float o = hadd2(o0) + hadd2(o1);
                o += __shfl_xor_sync(0xffffffffu, o, 1);
                o += __shfl_xor_sync(0xffffffffu, o, 2);
                if (quarter == 0)
                    core[(tbase + (size_t)blk * SCH + i) * VALD + h * DV + dv0 + col] = o;
            }

            NBAR(1, 256);
            if (blk + 2 < nblk) issue(blk + 2, buf);
            asm volatile("cp.async.commit_group;" ::: "memory");
        }
    } else {
        // ===================== z-GEMM half =====================
        const uint32_t sb = smem_u32(dynsm);
        const int gtid = tid - 256;
        const int lane = gtid & 31, wid = gtid >> 5;
        const int wm = (wid & 1) * 64, wn = (wid >> 1) * 32;
        const int grp = lane >> 2, qid = lane & 3;
        const uint32_t a_row = (uint32_t)(lane & 15);
        const uint32_t a_c16 = (uint32_t)((lane >> 4) * 16);
        const uint32_t b_row = (uint32_t)((lane & 7) + ((lane >> 4) & 1) * 8);
        const uint32_t b_c16 = (uint32_t)(((lane >> 3) & 1) * 16);
        const int niter = HID >> 5;   // 64

        for (int T = cid; T < ZTILES; T += (int)gridDim.x) {
            const int bm = (T & 31) * 128;
            const int zn = (T >> 5) * 128;     // z-col base within 4096

            NBAR(2, 256);   // previous tile fully consumed before refilling buffers

            float c[4][4][4];
            #pragma unroll
            for (int i = 0; i < 4; i++)
                #pragma unroll
                for (int j = 0; j < 4; j++)
                    #pragma unroll
                    for (int r = 0; r < 4; r++) c[i][j][r] = 0.f;

            auto issue = [&](int kblk, int buf) {
                const int k0 = kblk * 32;
                #pragma unroll
                for (int i = 0; i < 2; i++) {
                    int chunk = gtid + i * 256;
                    int row = chunk >> 2, c16 = chunk & 3;
                    size_t ga = (size_t)(bm + row) * HID + k0 + c16 * 8;
                    size_t gb = (size_t)(zn + row) * HID + k0 + c16 * 8;
                    uint32_t so = sb + buf * STAGE_B + row * TSTRIDE + c16 * 16;
                    cpasync16(so,              Ah + ga);
                    cpasync16(so + TILE_B,     Al + ga);
                    cpasync16(so + 2 * TILE_B, Bh + gb);
                    cpasync16(so + 3 * TILE_B, Bl + gb);
                }
            };

            issue(0, 0);
            asm volatile("cp.async.commit_group;" ::: "memory");
            issue(1, 1);
            asm volatile("cp.async.commit_group;" ::: "memory");

            for (int it = 0; it < niter; it++) {
                asm volatile("cp.async.wait_group 1;" ::: "memory");
                NBAR(2, 256);
                const int buf = it & 1;
                const uint32_t base = sb + buf * STAGE_B;

                #pragma unroll
                for (int ks = 0; ks < 2; ks++) {
                    const uint32_t koff = ks * 32;
                    const uint32_t abase = base + (uint32_t)(wm + a_row) * TSTRIDE + koff + a_c16;
                    const uint32_t bbase = base + 2 * TILE_B + (uint32_t)(wn + b_row) * TSTRIDE + koff + b_c16;
                    uint32_t ah[4][4], bh[2][4];
                    #pragma unroll
                    for (int i = 0; i < 4; i++) ldmx4(ah[i], abase + (uint32_t)(i * 16) * TSTRIDE);
                    #pragma unroll
                    for (int J = 0; J < 2; J++) ldmx4(bh[J], bbase + (uint32_t)(J * 16) * TSTRIDE);
                    #pragma unroll
                    for (int i = 0; i < 4; i++)
                        #pragma unroll
                        for (int j = 0; j < 4; j++) mma16816(c[i][j], ah[i], &bh[j >> 1][(j & 1) * 2]);
                    {
                        uint32_t al[4][4];
                        #pragma unroll
                        for (int i = 0; i < 4; i++) ldmx4(al[i], abase + TILE_B + (uint32_t)(i * 16) * TSTRIDE);
                        #pragma unroll
                        for (int i = 0; i < 4; i++)
                            #pragma unroll
                            for (int j = 0; j < 4; j++) mma16816(c[i][j], al[i], &bh[j >> 1][(j & 1) * 2]);
                    }
                    {
                        uint32_t bl[2][4];
                        #pragma unroll
                        for (int J = 0; J < 2; J++) ldmx4(bl[J], bbase + TILE_B + (uint32_t)(J * 16) * TSTRIDE);
                        #pragma unroll
                        for (int i = 0; i < 4; i++)
                            #pragma unroll
                            for (int j = 0; j < 4; j++) mma16816(c[i][j], ah[i], &bl[j >> 1][(j & 1) * 2]);
                    }
                }
                NBAR(2, 256);
                if (it + 2 < niter) issue(it + 2, buf);
                asm volatile("cp.async.commit_group;" ::: "memory");
            }

            #pragma unroll
            for (int i = 0; i < 4; i++) {
                const int row0 = bm + wm + i * 16 + grp;
                #pragma unroll
                for (int j = 0; j < 4; j++) {
                    const int col = 2 * KEYD + VALD + zn + wn + j * 8 + qid * 2;   // 8192 + ...
                    float2 v01 = make_float2(c[i][j][0], c[i][j][1]);
                    float2 v23 = make_float2(c[i][j][2], c[i][j][3]);
                    *(float2*)(qkvz + (size_t)row0 * PQKVZ + col)       = v01;
                    *(float2*)(qkvz + (size_t)(row0 + 8) * PQKVZ + col) = v23;
                }
            }
        }
    }
}

// ---------------- SIMT SGEMM (NT) for tiny ba GEMM ----------------
#define BM 128
#define BN 128
#define BKK 16
__global__ __launch_bounds__(256) void sgemm_nt(const float* __restrict__ A,
                                                const float* __restrict__ B,
                                                float* __restrict__ C,
                                                int M, int N, int K) {
    __shared__ float As[BKK][BM];
    __shared__ float Bs[BKK][BN];
    const int tid = threadIdx.x;
    const int bm = blockIdx.y * BM;
    const int bn = blockIdx.x * BN;
    const int tx = tid & 15;
    const int ty = tid >> 4;
    const int lrow = tid >> 2;
    const int lk4 = (tid & 3) * 4;

    float acc[8][8];
    #pragma unroll
    for (int i = 0; i < 8; i++)
        #pragma unroll
        for (int j = 0; j < 8; j++) acc[i][j] = 0.f;

    for (int k0 = 0; k0 < K; k0 += BKK) {
        #pragma unroll
        for (int it = 0; it < 2; it++) {
            int row = lrow + it * 64;
            float4 v = *(const float4*)(A + (size_t)(bm + row) * K + k0 + lk4);
            As[lk4 + 0][row] = v.x; As[lk4 + 1][row] = v.y;
            As[lk4 + 2][row] = v.z; As[lk4 + 3][row] = v.w;
        }
        #pragma unroll
        for (int it = 0; it < 2; it++) {
            int row = lrow + it * 64;
            int gn = bn + row;
            float4 v = make_float4(0.f, 0.f, 0.f, 0.f);
            if (gn < N) v = *(const float4*)(B + (size_t)gn * K + k0 + lk4);
            Bs[lk4 + 0][row] = v.x; Bs[lk4 + 1][row] = v.y;
            Bs[lk4 + 2][row] = v.z; Bs[lk4 + 3][row] = v.w;
        }
        __syncthreads();
        #pragma unroll
        for (int kk = 0; kk < BKK; kk++) {
            float ar[8], br[8];
            #pragma unroll
            for (int i = 0; i < 8; i++) ar[i] = As[kk][ty * 8 + i];
            #pragma unroll
            for (int j = 0; j < 8; j++) br[j] = Bs[kk][tx * 8 + j];
            #pragma unroll
            for (int i = 0; i < 8; i++)
                #pragma unroll
                for (int j = 0; j < 8; j++)
                    acc[i][j] = fmaf(ar[i], br[j], acc[i][j]);
        }
        __syncthreads();
    }
    #pragma unroll
    for (int i = 0; i < 8; i++) {
        int gm = bm + ty * 8 + i;
        #pragma unroll
        for (int j = 0; j < 8; j++) {
            int gn = bn + tx * 8 + j;
            if (gn < N) C[(size_t)gm * N + gn] = acc[i][j];
        }
    }
}

// ---------------- depthwise causal conv1d (K=4) + SiLU ----------------
__global__ void conv_silu_kernel(const float* __restrict__ qkvz,
                                 const float* __restrict__ cw,
                                 float* __restrict__ out) {
    size_t idx = (size_t)blockIdx.x * blockDim.x + threadIdx.x;
    int c = (int)(idx & (CONVD - 1));
    size_t t = idx >> 13;
    int s = (int)(t & (SEQ - 1));
    size_t b = t >> 11;
    const float* base = qkvz + (b * SEQ) * (size_t)PQKVZ + c;
    float w0 = cw[c * 4 + 0], w1 = cw[c * 4 + 1], w2 = cw[c * 4 + 2], w3 = cw[c * 4 + 3];
    float acc = w3 * base[(size_t)s * PQKVZ];
    if (s >= 1) acc = fmaf(w2, base[(size_t)(s - 1) * PQKVZ], acc);
    if (s >= 2) acc = fmaf(w1, base[(size_t)(s - 2) * PQKVZ], acc);
    if (s >= 3) acc = fmaf(w0, base[(size_t)(s - 3) * PQKVZ], acc);
    out[idx] = acc / (1.f + expf(-acc));
}

// ---------------- l2norm(q,k) + gates ----------------
__global__ __launch_bounds__(512) void prep_kernel(const float* __restrict__ conv,
                                                   const float* __restrict__ ba,
                                                   const float* __restrict__ dt_bias,
                                                   const float* __restrict__ A_log,
                                                   float* __restrict__ qn,
                                                   float* __restrict__ kn,
                                                   float* __restrict__ beta,
                                                   float* __restrict__ gdec) {
    size_t t = blockIdx.x;
    int w = threadIdx.x >> 5;
    int l = threadIdx.x & 31;
    const float* cq = conv + t * CONVD + w * DK;
    const float* ck = conv + t * CONVD + KEYD + w * DK;
    float qv[4], kv[4];
    float sq = 0.f, sk = 0.f;
    #pragma unroll
    for (int i = 0; i < 4; i++) {
        qv[i] = cq[l + 32 * i]; sq = fmaf(qv[i], qv[i], sq);
        kv[i] = ck[l + 32 * i]; sk = fmaf(kv[i], kv[i], sk);
    }
    #pragma unroll
    for (int o = 16; o; o >>= 1) {
        sq += __shfl_xor_sync(0xffffffffu, sq, o);
        sk += __shfl_xor_sync(0xffffffffu, sk, o);
    }
    float rq = rsqrtf(sq + EPSF), rk = rsqrtf(sk + EPSF);
    #pragma unroll
    for (int i = 0; i < 4; i++) {
        qn[(t * NK + w) * DK + l + 32 * i] = qv[i] * rq;
        kn[(t * NK + w) * DK + l + 32 * i] = kv[i] * rk;
    }
    if (threadIdx.x < NV) {
        int h = threadIdx.x;
        float bv = ba[t * 64 + h];
        float av = ba[t * 64 + NV + h];
        beta[t * NV + h] = 1.f / (1.f + expf(-bv));
        float xx = av + dt_bias[h];
        float sp = (xx > 20.f) ? xx : log1pf(expf(xx));
        gdec[t * NV + h] = expf(-expf(A_log[h]) * sp);
    }
}

// ---------------- RMSNorm(1+w) + silu(z) gate -> bf16 hi/lo ----------------
__global__ __launch_bounds__(256) void rmsnorm_gate_kernel(const float* __restrict__ core,
                                                           const float* __restrict__ qkvz,
                                                           const float* __restrict__ norm_w,
                                                           __nv_bfloat16* __restrict__ ghi,
                                                           __nv_bfloat16* __restrict__ glo) {
    size_t t = blockIdx.x;
    __shared__ float red[8];
    __shared__ float s_scale;
    const float* row = core + t * VALD;
    const float* zrow = qkvz + t * PQKVZ + 2 * KEYD + VALD;
    float ss = 0.f;
    for (int c = threadIdx.x; c < VALD; c += 256) { float v = row[c]; ss = fmaf(v, v, ss); }
    #pragma unroll
    for (int o = 16; o; o >>= 1) ss += __shfl_xor_sync(0xffffffffu, ss, o);
    if ((threadIdx.x & 31) == 0) red[threadIdx.x >> 5] = ss;
    __syncthreads();
    if (threadIdx.x == 0) {
        float tot = 0.f;
        #pragma unroll
        for (int i = 0; i < 8; i++) tot += red[i];
        s_scale = rsqrtf(tot * (1.f / VALD) + EPSF);
    }
    __syncthreads();
    float sc = s_scale;
    for (int c = threadIdx.x; c < VALD; c += 256) {
        float z = zrow[c];
        float sz = z / (1.f + expf(-z));
        float val = row[c] * sc * (1.f + norm_w[c]) * sz;
        __nv_bfloat16 hv = __float2bfloat16(val);
        ghi[t * VALD + c] = hv;
        glo[t * VALD + c] = __float2bfloat16(val - __bfloat162float(hv));
    }
}

// ---------------- launch ----------------
extern "C" void kernel_launch(void* const* d_in, const int* in_sizes, int n_in,
                              void* d_out, int out_size) {
    const float* x       = (const float*)d_in[0];
    const float* W_qkvz  = (const float*)d_in[1];
    const float* W_ba    = (const float*)d_in[2];
    const float* conv_w  = (const float*)d_in[3];
    const float* dt_bias = (const float*)d_in[4];
    const float* A_log   = (const float*)d_in[5];
    const float* norm_w  = (const float*)d_in[6];
    const float* W_out   = (const float*)d_in[7];
    float* out = (float*)d_out;

    float *p_qkvz, *p_ba, *p_conv, *p_qn, *p_kn, *p_beta, *p_g, *p_core;
    __nv_bfloat16 *p_xhi, *p_xlo, *p_w1hi, *p_w1lo, *p_w2hi, *p_w2lo, *p_ghi, *p_glo;
    cudaGetSymbolAddress((void**)&p_qkvz,  g_qkvz);
    cudaGetSymbolAddress((void**)&p_ba,    g_ba);
    cudaGetSymbolAddress((void**)&p_conv,  g_conv);
    cudaGetSymbolAddress((void**)&p_qn,    g_qn);
    cudaGetSymbolAddress((void**)&p_kn,    g_kn);
    cudaGetSymbolAddress((void**)&p_beta,  g_beta);
    cudaGetSymbolAddress((void**)&p_g,     g_gdec);
    cudaGetSymbolAddress((void**)&p_core,  g_core);
    cudaGetSymbolAddress((void**)&p_xhi,  g_xhi);
    cudaGetSymbolAddress((void**)&p_xlo,  g_xlo);
    cudaGetSymbolAddress((void**)&p_w1hi, g_w1hi);
    cudaGetSymbolAddress((void**)&p_w1lo, g_w1lo);
    cudaGetSymbolAddress((void**)&p_w2hi, g_w2hi);
    cudaGetSymbolAddress((void**)&p_w2lo, g_w2lo);
    cudaGetSymbolAddress((void**)&p_ghi,  g_ghi);
    cudaGetSymbolAddress((void**)&p_glo,  g_glo);

    cudaFuncSetAttribute(gemm_bf16x3, cudaFuncAttributeMaxDynamicSharedMemorySize, GSMEM);
    cudaFuncSetAttribute(scan_zgemm, cudaFuncAttributeMaxDynamicSharedMemorySize, GSMEM);

    // splits for GEMM operands
    split_bf16<<<(TOK * (size_t)HID) / 1024, 256>>>(x, p_xhi, p_xlo);
    split_bf16<<<((size_t)PQKVZ * HID) / 1024, 256>>>(W_qkvz, p_w1hi, p_w1lo);
    split_bf16<<<((size_t)HID * VALD) / 1024, 256>>>(W_out, p_w2hi, p_w2lo);

    // 1) qkv part of qkvz = x @ W_qkvz[0:8192]^T  (z columns deferred to fused kernel)
    gemm_bf16x3<<<dim3(TOK / 128, CONVD / 128), 256, GSMEM>>>(
        p_xhi, p_xlo, p_w1hi, p_w1lo, p_qkvz, TOK, CONVD, HID, PQKVZ);
    // 2) ba = x @ W_ba^T (SIMT, tiny)
    sgemm_nt<<<dim3(1, TOK / BM), 256>>>(x, W_ba, p_ba, TOK, 64, HID);
    // 3) conv + silu
    conv_silu_kernel<<<(TOK * (size_t)CONVD) / 256, 256>>>(p_qkvz, conv_w, p_conv);
    // 4) l2norm + gates
    prep_kernel<<<TOK, 512>>>(p_conv, p_ba, dt_bias, A_log, p_qn, p_kn, p_beta, p_g);
    // 5) fused: delta-rule scan (warps 0-7) + z-GEMM (warps 8-15)
    scan_zgemm<<<144, 512, GSMEM>>>(p_qn, p_kn, p_conv, p_beta, p_g, p_core,
                                    p_xhi, p_xlo,
                                    p_w1hi + (size_t)CONVD * HID, p_w1lo + (size_t)CONVD * HID,
                                    p_qkvz);
    // 6) rmsnorm + gate -> bf16 hi/lo directly
    rmsnorm_gate_kernel<<<TOK, 256>>>(p_core, p_qkvz, norm_w, p_ghi, p_glo);
    // 7) out = gated @ W_out^T
    gemm_bf16x3<<<dim3(TOK / 128, HID / 128), 256, GSMEM>>>(
        p_ghi, p_glo, p_w2hi, p_w2lo, out, TOK, HID, VALD, HID);
}

// round 13
// speedup vs baseline: 1.0661x; 1.0125x over previous
#include <cuda_runtime.h>
#include <cuda_bf16.h>
#include <cstdint>

// ---------------- model dims ----------------
#define BATCH 2
#define SEQ   2048
#define TOK   (BATCH*SEQ)        // 4096
#define HID   2048
#define NK    16
#define NV    32
#define DK    128
#define DV    128
#define KEYD  2048               // NK*DK
#define VALD  4096               // NV*DV
#define CONVD 8192               // 2*KEYD + VALD
#define PQKVZ 12288              // 2*KEYD + 2*VALD
#define EPSF  1e-6f

// ---------------- scratch (device globals; no allocation) ----------------
__device__ float g_qkvz [(size_t)TOK * PQKVZ];
__device__ float g_ba   [(size_t)TOK * 64];
__device__ float g_conv [(size_t)TOK * CONVD];
__device__ float g_qn   [(size_t)TOK * KEYD];
__device__ float g_kn   [(size_t)TOK * KEYD];
__device__ float g_beta [(size_t)TOK * NV];
__device__ float g_gdec [(size_t)TOK * NV];
__device__ float g_core [(size_t)TOK * VALD];
__device__ int   g_tile_ctr;
// bf16 hi/lo split scratch
__device__ __nv_bfloat16 g_xhi [(size_t)TOK * HID];
__device__ __nv_bfloat16 g_xlo [(size_t)TOK * HID];
__device__ __nv_bfloat16 g_w1hi[(size_t)PQKVZ * HID];
__device__ __nv_bfloat16 g_w1lo[(size_t)PQKVZ * HID];
__device__ __nv_bfloat16 g_w2hi[(size_t)HID * VALD];
__device__ __nv_bfloat16 g_w2lo[(size_t)HID * VALD];
__device__ __nv_bfloat16 g_ghi [(size_t)TOK * VALD];
__device__ __nv_bfloat16 g_glo [(size_t)TOK * VALD];

// ---------------- helpers ----------------
__device__ __forceinline__ uint32_t smem_u32(const void* p) {
    uint32_t r;
    asm("{ .reg .u64 t; cvta.to.shared.u64 t, %1; cvt.u32.u64 %0, t; }" : "=r"(r) : "l"(p));
    return r;
}
__device__ __forceinline__ void cpasync16(uint32_t s, const void* g) {
    asm volatile("cp.async.cg.shared.global [%0], [%1], 16;" :: "r"(s), "l"(g));
}
__device__ __forceinline__ void cpasync4(uint32_t s, const void* g) {
    asm volatile("cp.async.ca.shared.global [%0], [%1], 4;" :: "r"(s), "l"(g));
}
__device__ __forceinline__ void ldmx4(uint32_t* r, uint32_t addr) {
    asm volatile("ldmatrix.sync.aligned.m8n8.x4.shared.b16 {%0,%1,%2,%3}, [%4];"
                 : "=r"(r[0]), "=r"(r[1]), "=r"(r[2]), "=r"(r[3]) : "r"(addr));
}
__device__ __forceinline__ void mma16816(float* c, const uint32_t* a, const uint32_t* b) {
    asm volatile(
        "mma.sync.aligned.m16n8k16.row.col.f32.bf16.bf16.f32 "
        "{%0,%1,%2,%3}, {%4,%5,%6,%7}, {%8,%9}, {%0,%1,%2,%3};"
        : "+f"(c[0]), "+f"(c[1]), "+f"(c[2]), "+f"(c[3])
        : "r"(a[0]), "r"(a[1]), "r"(a[2]), "r"(a[3]), "r"(b[0]), "r"(b[1]));
}
// f32x2 packed math
__device__ __forceinline__ unsigned long long pk2(float a, float b) {
    unsigned long long r; asm("mov.b64 %0, {%1, %2};" : "=l"(r) : "f"(a), "f"(b)); return r;
}
__device__ __forceinline__ unsigned long long fma2(unsigned long long a, unsigned long long b, unsigned long long c) {
    unsigned long long d; asm("fma.rn.f32x2 %0, %1, %2, %3;" : "=l"(d) : "l"(a), "l"(b), "l"(c)); return d;
}
__device__ __forceinline__ unsigned long long mul2(unsigned long long a, unsigned long long b) {
    unsigned long long d; asm("mul.rn.f32x2 %0, %1, %2;" : "=l"(d) : "l"(a), "l"(b)); return d;
}
__device__ __forceinline__ float hadd2(unsigned long long v) {
    float a, b; asm("mov.b64 {%0, %1}, %2;" : "=f"(a), "=f"(b) : "l"(v)); return a + b;
}
// named barriers (warp-aligned thread groups)
#define NBAR(id, cnt) asm volatile("bar.sync %0, %1;" :: "r"(id), "r"(cnt) : "memory")

// ---------------- split fp32 -> bf16 hi/lo ----------------
__global__ __launch_bounds__(256) void split_bf16(const float* __restrict__ src,
                                                  __nv_bfloat16* __restrict__ hi,
                                                  __nv_bfloat16* __restrict__ lo) {
    size_t i = ((size_t)blockIdx.x * blockDim.x + threadIdx.x) * 4;
    float4 v = *(const float4*)(src + i);
    __nv_bfloat16 h0 = __float2bfloat16(v.x), h1 = __float2bfloat16(v.y);
    __nv_bfloat16 h2 = __float2bfloat16(v.z), h3 = __float2bfloat16(v.w);
    __nv_bfloat16 l0 = __float2bfloat16(v.x - __bfloat162float(h0));
    __nv_bfloat16 l1 = __float2bfloat16(v.y - __bfloat162float(h1));
    __nv_bfloat16 l2 = __float2bfloat16(v.z - __bfloat162float(h2));
    __nv_bfloat16 l3 = __float2bfloat16(v.w - __bfloat162float(h3));
    __nv_bfloat162* hp = (__nv_bfloat162*)(hi + i);
    __nv_bfloat162* lp = (__nv_bfloat162*)(lo + i);
    hp[0] = __nv_bfloat162(h0, h1); hp[1] = __nv_bfloat162(h2, h3);
    lp[0] = __nv_bfloat162(l0, l1); lp[1] = __nv_bfloat162(l2, l3);
}

// ---------------- mma.sync bf16x3 GEMM (NT): C[m,n(ldc)] = sum_k A[m,k]*B[n,k] ----------------
#define TSTRIDE 80
#define TILE_B  (128 * TSTRIDE)
#define STAGE_B (4 * TILE_B)
#define GSMEM   (2 * STAGE_B)

__global__ __launch_bounds__(256, 2)
void gemm_bf16x3(const __nv_bfloat16* __restrict__ Ah, const __nv_bfloat16* __restrict__ Al,
                 const __nv_bfloat16* __restrict__ Bh, const __nv_bfloat16* __restrict__ Bl,
                 float* __restrict__ C, int M, int N, int K, int ldc) {
    extern __shared__ __align__(16) char sm[];
    const uint32_t sb = smem_u32(sm);
    const int tid = threadIdx.x;
    const int lane = tid & 31, wid = tid >> 5;
    const int bm = blockIdx.x * 128, bn = blockIdx.y * 128;
    const int wm = (wid & 1) * 64, wn = (wid >> 1) * 32;
    const int grp = lane >> 2, qid = lane & 3;

    const uint32_t a_row = (uint32_t)(lane & 15);
    const uint32_t a_c16 = (uint32_t)((lane >> 4) * 16);
    const uint32_t b_row = (uint32_t)((lane & 7) + ((lane >> 4) & 1) * 8);
    const uint32_t b_c16 = (uint32_t)(((lane >> 3) & 1) * 16);

    float c[4][4][4];
    #pragma unroll
    for (int i = 0; i < 4; i++)
        #pragma unroll
        for (int j = 0; j < 4; j++)
            #pragma unroll
            for (int r = 0; r < 4; r++) c[i][j][r] = 0.f;

    const int niter = K >> 5;

    auto issue = [&](int kblk, int buf) {
        const int k0 = kblk * 32;
        #pragma unroll
        for (int i = 0; i < 2; i++) {
            int chunk = tid + i * 256;
            int row = chunk >> 2, c16 = chunk & 3;
            size_t ga = (size_t)(bm + row) * K + k0 + c16 * 8;
            size_t gb = (size_t)(bn + row) * K + k0 + c16 * 8;
            uint32_t so = sb + buf * STAGE_B + row * TSTRIDE + c16 * 16;
            cpasync16(so,              Ah + ga);
            cpasync16(so + TILE_B,     Al + ga);
            cpasync16(so + 2 * TILE_B, Bh + gb);
            cpasync16(so + 3 * TILE_B, Bl + gb);
        }
    };

    issue(0, 0);
    asm volatile("cp.async.commit_group;" ::: "memory");
    issue(1, 1);
    asm volatile("cp.async.commit_group;" ::: "memory");

    for (int it = 0; it < niter; it++) {
        asm volatile("cp.async.wait_group 1;" ::: "memory");
        __syncthreads();
        const int buf = it & 1;
        const uint32_t base = sb + buf * STAGE_B;

        #pragma unroll
        for (int ks = 0; ks < 2; ks++) {
            const uint32_t koff = ks * 32;
            const uint32_t abase = base + (uint32_t)(wm + a_row) * TSTRIDE + koff + a_c16;
            const uint32_t bbase = base + 2 * TILE_B + (uint32_t)(wn + b_row) * TSTRIDE + koff + b_c16;
            uint32_t ah[4][4], bh[2][4];
            #pragma unroll
            for (int i = 0; i < 4; i++) ldmx4(ah[i], abase + (uint32_t)(i * 16) * TSTRIDE);
            #pragma unroll
            for (int J = 0; J < 2; J++) ldmx4(bh[J], bbase + (uint32_t)(J * 16) * TSTRIDE);
            #pragma unroll
            for (int i = 0; i < 4; i++)
                #pragma unroll
                for (int j = 0; j < 4; j++) mma16816(c[i][j], ah[i], &bh[j >> 1][(j & 1) * 2]);
            {
                uint32_t al[4][4];
                #pragma unroll
                for (int i = 0; i < 4; i++) ldmx4(al[i], abase + TILE_B + (uint32_t)(i * 16) * TSTRIDE);
                #pragma unroll
                for (int i = 0; i < 4; i++)
                    #pragma unroll
                    for (int j = 0; j < 4; j++) mma16816(c[i][j], al[i], &bh[j >> 1][(j & 1) * 2]);
            }
            {
                uint32_t bl[2][4];
                #pragma unroll
                for (int J = 0; J < 2; J++) ldmx4(bl[J], bbase + TILE_B + (uint32_t)(J * 16) * TSTRIDE);
                #pragma unroll
                for (int i = 0; i < 4; i++)
                    #pragma unroll
                    for (int j = 0; j < 4; j++) mma16816(c[i][j], ah[i], &bl[j >> 1][(j & 1) * 2]);
            }
        }
        __syncthreads();
        if (it + 2 < niter) issue(it + 2, buf);
        asm volatile("cp.async.commit_group;" ::: "memory");
    }

    #pragma unroll
    for (int i = 0; i < 4; i++) {
        const int row0 = bm + wm + i * 16 + grp;
        #pragma unroll
        for (int j = 0; j < 4; j++) {
            const int col = bn + wn + j * 8 + qid * 2;
            float2 v01 = make_float2(c[i][j][0], c[i][j][1]);
            float2 v23 = make_float2(c[i][j][2], c[i][j][3]);
            *(float2*)(C + (size_t)row0 * ldc + col)       = v01;
            *(float2*)(C + (size_t)(row0 + 8) * ldc + col) = v23;
        }
    }
}

// ---------------- fused scan + z-GEMM (warp-specialized, dynamic tiles) ----------------
// grid 148, 512 threads. Threads 0..255 (cid<128): delta-rule scan v5 (NBAR 1).
// Threads 256..511: z-GEMM tiles via global atomic counter (NBAR 2, dynamic smem).
#define SCH   8
#define KROW  144   // 4 quarters * 36 floats
#define ZTILES 1024 // 32 (M) x 32 (N)

__global__ __launch_bounds__(512)
void scan_zgemm(const float* __restrict__ qn, const float* __restrict__ kn,
                const float* __restrict__ conv, const float* __restrict__ beta,
                const float* __restrict__ gdec, float* __restrict__ core,
                const __nv_bfloat16* __restrict__ Ah, const __nv_bfloat16* __restrict__ Al,
                const __nv_bfloat16* __restrict__ Bh, const __nv_bfloat16* __restrict__ Bl,
                float* __restrict__ qkvz) {
    extern __shared__ __align__(16) char dynsm[];        // 81920 B for gemm
    __shared__ float ksm[2][SCH][KROW];
    __shared__ float qsm[2][SCH][KROW];
    __shared__ float vsm[2][SCH][64];
    __shared__ float gsm[2][SCH], bsm[2][SCH];
    __shared__ int s_tile;

    const int cid = blockIdx.x;
    const int tid = threadIdx.x;

    if (tid < 256) {
        // ===================== SCAN half (cid < 128) =====================
        if (cid >= 128) return;
        const int h   = cid & 31;
        const int dv0 = ((cid >> 5) & 1) * 64;
        const int b   = cid >> 6;
        const int nk = h >> 1;
        const int col = tid >> 2;
        const int quarter = tid & 3;

        unsigned long long st[16];
        #pragma unroll
        for (int j = 0; j < 16; j++) st[j] = 0ull;

        const size_t tbase = (size_t)b * SEQ;
        const int krow_t = tid >> 5, kln = tid & 31;
        const int kqoff = (kln >> 3) * 36 + (kln & 7) * 4;

        auto issue = [&](int blk, int buf) {
            const size_t t0 = tbase + (size_t)blk * SCH;
            cpasync16(smem_u32(&ksm[buf][krow_t][kqoff]), kn + ((t0 + krow_t) * NK + nk) * DK + kln * 4);
            cpasync16(smem_u32(&qsm[buf][krow_t][kqoff]), qn + ((t0 + krow_t) * NK + nk) * DK + kln * 4);
            if (tid < 128) {
                int vr = tid >> 4, vc = (tid & 15) * 4;
                cpasync16(smem_u32(&vsm[buf][vr][vc]),
                          conv + (t0 + vr) * CONVD + 2 * KEYD + h * DV + dv0 + vc);
            } else if (tid < 128 + SCH) {
                cpasync4(smem_u32(&gsm[buf][tid - 128]), gdec + (t0 + tid - 128) * NV + h);
            } else if (tid < 128 + 2 * SCH) {
                cpasync4(smem_u32(&bsm[buf][tid - 128 - SCH]), beta + (t0 + tid - 128 - SCH) * NV + h);
            }
        };

        issue(0, 0);
        asm volatile("cp.async.commit_group;" ::: "memory");
        issue(1, 1);
        asm volatile("cp.async.commit_group;" ::: "memory");

        const int nblk = SEQ / SCH;
        for (int blk = 0; blk < nblk; blk++) {
            const int buf = blk & 1;
            asm volatile("cp.async.wait_group 1;" ::: "memory");
            NBAR(1, 256);

            #pragma unroll
            for (int i = 0; i < SCH; i++) {
                const ulonglong2* kk = (const ulonglong2*)&ksm[buf][i][quarter * 36];
                const ulonglong2* qq = (const ulonglong2*)&qsm[buf][i][quarter * 36];
                float vt = vsm[buf][i][col];
                float ge = gsm[buf][i];
                float bt = bsm[buf][i];

                unsigned long long a0 = 0ull, a1 = 0ull;
                #pragma unroll
                for (int j = 0; j < 8; j++) {
                    ulonglong2 kj = kk[j];
                    a0 = fma2(kj.x, st[2 * j + 0], a0);
                    a1 = fma2(kj.y, st[2 * j + 1], a1);
                }
                float kvd = hadd2(a0) + hadd2(a1);
                kvd += __shfl_xor_sync(0xffffffffu, kvd, 1);
                kvd += __shfl_xor_sync(0xffffffffu, kvd, 2);
                float delta = bt * (vt - ge * kvd);
                unsigned long long ge2 = pk2(ge, ge);
                unsigned long long d2 = pk2(delta, delta);

                unsigned long long o0 = 0ull, o1 = 0ull;
                #pragma unroll
                for (int j = 0; j < 8; j++) {
                    ulonglong2 kj = kk[j], qj = qq[j];
                    st[2 * j + 0] = fma2(ge2, st[2 * j + 0], mul2(kj.x, d2));
                    o0 = fma2(qj.x, st[2 * j + 0], o0);
                    st[2 * j + 1] = fma2(ge2, st[2 * j + 1], mul2(kj.y, d2));
                    o1 = fma2(qj.y, st[2 * j + 1], o1);
                }
                float o = hadd2(o0) + hadd2(o1);
                o += __shfl_xor_sync(0xffffffffu, o, 1);
                o += __shfl_xor_sync(0xffffffffu, o, 2);
                if (quarter == 0)
                    core[(tbase + (size_t)blk * SCH + i) * VALD + h * DV + dv0 + col] = o;
            }

            NBAR(1, 256);
            if (blk + 2 < nblk) issue(blk + 2, buf);
            asm volatile("cp.async.commit_group;" ::: "memory");
        }
    } else {
        // ===================== z-GEMM half (dynamic tile scheduler) =====================
        const uint32_t sb = smem_u32(dynsm);
        const int gtid = tid - 256;
        const int lane = gtid & 31, wid = gtid >> 5;
        const int wm = (wid & 1) * 64, wn = (wid >> 1) * 32;
        const int grp = lane >> 2, qid = lane & 3;
        const uint32_t a_row = (uint32_t)(lane & 15);
        const uint32_t a_c16 = (uint32_t)((lane >> 4) * 16);
        const uint32_t b_row = (uint32_t)((lane & 7) + ((lane >> 4) & 1) * 8);
        const uint32_t b_c16 = (uint32_t)(((lane >> 3) & 1) * 16);
        const int niter = HID >> 5;   // 64

        for (;;) {
            NBAR(2, 256);   // prev tile fully consumed before grabbing next + refilling buffers
            if (gtid == 0) s_tile = atomicAdd(&g_tile_ctr, 1);
            NBAR(2, 256);
            const int T = s_tile;
            if (T >= ZTILES) break;

            const int bm = (T & 31) * 128;
            const int zn = (T >> 5) * 128;     // z-col base within 4096

            float c[4][4][4];
            #pragma unroll
            for (int i = 0; i < 4; i++)
                #pragma unroll
                for (int j = 0; j < 4; j++)
                    #pragma unroll
                    for (int r = 0; r < 4; r++) c[i][j][r] = 0.f;

            auto issue = [&](int kblk, int buf) {
                const int k0 = kblk * 32;
                #pragma unroll
                for (int i = 0; i < 2; i++) {
                    int chunk = gtid + i * 256;
                    int row = chunk >> 2, c16 = chunk & 3;
                    size_t ga = (size_t)(bm + row) * HID + k0 + c16 * 8;
                    size_t gb = (size_t)(zn + row) * HID + k0 + c16 * 8;
                    uint32_t so = sb + buf * STAGE_B + row * TSTRIDE + c16 * 16;
                    cpasync16(so,              Ah + ga);
                    cpasync16(so + TILE_B,     Al + ga);
                    cpasync16(so + 2 * TILE_B, Bh + gb);
                    cpasync16(so + 3 * TILE_B, Bl + gb);
                }
            };

            issue(0, 0);
            asm volatile("cp.async.commit_group;" ::: "memory");
            issue(1, 1);
            asm volatile("cp.async.commit_group;" ::: "memory");

            for (int it = 0; it < niter; it++) {
                asm volatile("cp.async.wait_group 1;" ::: "memory");
                NBAR(2, 256);
                const int buf = it & 1;
                const uint32_t base = sb + buf * STAGE_B;

                #pragma unroll
                for (int ks = 0; ks < 2; ks++) {
                    const uint32_t koff = ks * 32;
                    const uint32_t abase = base + (uint32_t)(wm + a_row) * TSTRIDE + koff + a_c16;
                    const uint32_t bbase = base + 2 * TILE_B + (uint32_t)(wn + b_row) * TSTRIDE + koff + b_c16;
                    uint32_t ah[4][4], bh[2][4];
                    #pragma unroll
                    for (int i = 0; i < 4; i++) ldmx4(ah[i], abase + (uint32_t)(i * 16) * TSTRIDE);
                    #pragma unroll
                    for (int J = 0; J < 2; J++) ldmx4(bh[J], bbase + (uint32_t)(J * 16) * TSTRIDE);
                    #pragma unroll
                    for (int i = 0; i < 4; i++)
                        #pragma unroll
                        for (int j = 0; j < 4; j++) mma16816(c[i][j], ah[i], &bh[j >> 1][(j & 1) * 2]);
                    {
                        uint32_t al[4][4];
                        #pragma unroll
                        for (int i = 0; i < 4; i++) ldmx4(al[i], abase + TILE_B + (uint32_t)(i * 16) * TSTRIDE);
                        #pragma unroll
                        for (int i = 0; i < 4; i++)
                            #pragma unroll
                            for (int j = 0; j < 4; j++) mma16816(c[i][j], al[i], &bh[j >> 1][(j & 1) * 2]);
                    }
                    {
                        uint32_t bl[2][4];
                        #pragma unroll
                        for (int J = 0; J < 2; J++) ldmx4(bl[J], bbase + TILE_B + (uint32_t)(J * 16) * TSTRIDE);
                        #pragma unroll
                        for (int i = 0; i < 4; i++)
                            #pragma unroll
                            for (int j = 0; j < 4; j++) mma16816(c[i][j], ah[i], &bl[j >> 1][(j & 1) * 2]);
                    }
                }
                NBAR(2, 256);
                if (it + 2 < niter) issue(it + 2, buf);
                asm volatile("cp.async.commit_group;" ::: "memory");
            }

            #pragma unroll
            for (int i = 0; i < 4; i++) {
                const int row0 = bm + wm + i * 16 + grp;
                #pragma unroll
                for (int j = 0; j < 4; j++) {
                    const int col = 2 * KEYD + VALD + zn + wn + j * 8 + qid * 2;   // 8192 + ...
                    float2 v01 = make_float2(c[i][j][0], c[i][j][1]);
                    float2 v23 = make_float2(c[i][j][2], c[i][j][3]);
                    *(float2*)(qkvz + (size_t)row0 * PQKVZ + col)       = v01;
                    *(float2*)(qkvz + (size_t)(row0 + 8) * PQKVZ + col) = v23;
                }
            }
        }
    }
}

// ---------------- SIMT SGEMM (NT) for tiny ba GEMM ----------------
#define BM 128
#define BN 128
#define BKK 16
__global__ __launch_bounds__(256) void sgemm_nt(const float* __restrict__ A,
                                                const float* __restrict__ B,
                                                float* __restrict__ C,
                                                int M, int N, int K) {
    __shared__ float As[BKK][BM];
    __shared__ float Bs[BKK][BN];
    const int tid = threadIdx.x;
    const int bm = blockIdx.y * BM;
    const int bn = blockIdx.x * BN;
    const int tx = tid & 15;
    const int ty = tid >> 4;
    const int lrow = tid >> 2;
    const int lk4 = (tid & 3) * 4;

    float acc[8][8];
    #pragma unroll
    for (int i = 0; i < 8; i++)
        #pragma unroll
        for (int j = 0; j < 8; j++) acc[i][j] = 0.f;

    for (int k0 = 0; k0 < K; k0 += BKK) {
        #pragma unroll
        for (int it = 0; it < 2; it++) {
            int row = lrow + it * 64;
            float4 v = *(const float4*)(A + (size_t)(bm + row) * K + k0 + lk4);
            As[lk4 + 0][row] = v.x; As[lk4 + 1][row] = v.y;
            As[lk4 + 2][row] = v.z; As[lk4 + 3][row] = v.w;
        }
        #pragma unroll
        for (int it = 0; it < 2; it++) {
            int row = lrow + it * 64;
            int gn = bn + row;
            float4 v = make_float4(0.f, 0.f, 0.f, 0.f);
            if (gn < N) v = *(const float4*)(B + (size_t)gn * K + k0 + lk4);
            Bs[lk4 + 0][row] = v.x; Bs[lk4 + 1][row] = v.y;
            Bs[lk4 + 2][row] = v.z; Bs[lk4 + 3][row] = v.w;
        }
        __syncthreads();
        #pragma unroll
        for (int kk = 0; kk < BKK; kk++) {
            float ar[8], br[8];
            #pragma unroll
            for (int i = 0; i < 8; i++) ar[i] = As[kk][ty * 8 + i];
            #pragma unroll
            for (int j = 0; j < 8; j++) br[j] = Bs[kk][tx * 8 + j];
            #pragma unroll
            for (int i = 0; i < 8; i++)
                #pragma unroll
                for (int j = 0; j < 8; j++)
                    acc[i][j] = fmaf(ar[i], br[j], acc[i][j]);
        }
        __syncthreads();
    }
    #pragma unroll
    for (int i = 0; i < 8; i++) {
        int gm = bm + ty * 8 + i;
        #pragma unroll
        for (int j = 0; j < 8; j++) {
            int gn = bn + tx * 8 + j;
            if (gn < N) C[(size_t)gm * N + gn] = acc[i][j];
        }
    }
}

// ---------------- depthwise causal conv1d (K=4) + SiLU ----------------
__global__ void conv_silu_kernel(const float* __restrict__ qkvz,
                                 const float* __restrict__ cw,
                                 float* __restrict__ out) {
    size_t idx = (size_t)blockIdx.x * blockDim.x + threadIdx.x;
    int c = (int)(idx & (CONVD - 1));
    size_t t = idx >> 13;
    int s = (int)(t & (SEQ - 1));
    size_t b = t >> 11;
    const float* base = qkvz + (b * SEQ) * (size_t)PQKVZ + c;
    float w0 = cw[c * 4 + 0], w1 = cw[c * 4 + 1], w2 = cw[c * 4 + 2], w3 = cw[c * 4 + 3];
    float acc = w3 * base[(size_t)s * PQKVZ];
    if (s >= 1) acc = fmaf(w2, base[(size_t)(s - 1) * PQKVZ], acc);
    if (s >= 2) acc = fmaf(w1, base[(size_t)(s - 2) * PQKVZ], acc);
    if (s >= 3) acc = fmaf(w0, base[(size_t)(s - 3) * PQKVZ], acc);
    out[idx] = acc / (1.f + expf(-acc));
}

// ---------------- l2norm(q,k) + gates ----------------
__global__ __launch_bounds__(512) void prep_kernel(const float* __restrict__ conv,
                                                   const float* __restrict__ ba,
                                                   const float* __restrict__ dt_bias,
                                                   const float* __restrict__ A_log,
                                                   float* __restrict__ qn,
                                                   float* __restrict__ kn,
                                                   float* __restrict__ beta,
                                                   float* __restrict__ gdec) {
    size_t t = blockIdx.x;
    int w = threadIdx.x >> 5;
    int l = threadIdx.x & 31;
    const float* cq = conv + t * CONVD + w * DK;
    const float* ck = conv + t * CONVD + KEYD + w * DK;
    float qv[4], kv[4];
    float sq = 0.f, sk = 0.f;
    #pragma unroll
    for (int i = 0; i < 4; i++) {
        qv[i] = cq[l + 32 * i]; sq = fmaf(qv[i], qv[i], sq);
        kv[i] = ck[l + 32 * i]; sk = fmaf(kv[i], kv[i], sk);
    }
    #pragma unroll
    for (int o = 16; o; o >>= 1) {
        sq += __shfl_xor_sync(0xffffffffu, sq, o);
        sk += __shfl_xor_sync(0xffffffffu, sk, o);
    }
    float rq = rsqrtf(sq + EPSF), rk = rsqrtf(sk + EPSF);
    #pragma unroll
    for (int i = 0; i < 4; i++) {
        qn[(t * NK + w) * DK + l + 32 * i] = qv[i] * rq;
        kn[(t * NK + w) * DK + l + 32 * i] = kv[i] * rk;
    }
    if (threadIdx.x < NV) {
        int h = threadIdx.x;
        float bv = ba[t * 64 + h];
        float av = ba[t * 64 + NV + h];
        beta[t * NV + h] = 1.f / (1.f + expf(-bv));
        float xx = av + dt_bias[h];
        float sp = (xx > 20.f) ? xx : log1pf(expf(xx));
        gdec[t * NV + h] = expf(-expf(A_log[h]) * sp);
    }
}

// ---------------- RMSNorm(1+w) + silu(z) gate -> bf16 hi/lo ----------------
__global__ __launch_bounds__(256) void rmsnorm_gate_kernel(const float* __restrict__ core,
                                                           const float* __restrict__ qkvz,
                                                           const float* __restrict__ norm_w,
                                                           __nv_bfloat16* __restrict__ ghi,
                                                           __nv_bfloat16* __restrict__ glo) {
    size_t t = blockIdx.x;
    __shared__ float red[8];
    __shared__ float s_scale;
    const float* row = core + t * VALD;
    const float* zrow = qkvz + t * PQKVZ + 2 * KEYD + VALD;
    float ss = 0.f;
    for (int c = threadIdx.x; c < VALD; c += 256) { float v = row[c]; ss = fmaf(v, v, ss); }
    #pragma unroll
    for (int o = 16; o; o >>= 1) ss += __shfl_xor_sync(0xffffffffu, ss, o);
    if ((threadIdx.x & 31) == 0) red[threadIdx.x >> 5] = ss;
    __syncthreads();
    if (threadIdx.x == 0) {
        float tot = 0.f;
        #pragma unroll
        for (int i = 0; i < 8; i++) tot += red[i];
        s_scale = rsqrtf(tot * (1.f / VALD) + EPSF);
    }
    __syncthreads();
    float sc = s_scale;
    for (int c = threadIdx.x; c < VALD; c += 256) {
        float z = zrow[c];
        float sz = z / (1.f + expf(-z));
        float val = row[c] * sc * (1.f + norm_w[c]) * sz;
        __nv_bfloat16 hv = __float2bfloat16(val);
        ghi[t * VALD + c] = hv;
        glo[t * VALD + c] = __float2bfloat16(val - __bfloat162float(hv));
    }
}

// ---------------- launch ----------------
extern "C" void kernel_launch(void* const* d_in, const int* in_sizes, int n_in,
                              void* d_out, int out_size) {
    const float* x       = (const float*)d_in[0];
    const float* W_qkvz  = (const float*)d_in[1];
    const float* W_ba    = (const float*)d_in[2];
    const float* conv_w  = (const float*)d_in[3];
    const float* dt_bias = (const float*)d_in[4];
    const float* A_log   = (const float*)d_in[5];
    const float* norm_w  = (const float*)d_in[6];
    const float* W_out   = (const float*)d_in[7];
    float* out = (float*)d_out;

    float *p_qkvz, *p_ba, *p_conv, *p_qn, *p_kn, *p_beta, *p_g, *p_core;
    int* p_ctr;
    __nv_bfloat16 *p_xhi, *p_xlo, *p_w1hi, *p_w1lo, *p_w2hi, *p_w2lo, *p_ghi, *p_glo;
    cudaGetSymbolAddress((void**)&p_qkvz,  g_qkvz);
    cudaGetSymbolAddress((void**)&p_ba,    g_ba);
    cudaGetSymbolAddress((void**)&p_conv,  g_conv);
    cudaGetSymbolAddress((void**)&p_qn,    g_qn);
    cudaGetSymbolAddress((void**)&p_kn,    g_kn);
    cudaGetSymbolAddress((void**)&p_beta,  g_beta);
    cudaGetSymbolAddress((void**)&p_g,     g_gdec);
    cudaGetSymbolAddress((void**)&p_core,  g_core);
    cudaGetSymbolAddress((void**)&p_ctr,   g_tile_ctr);
    cudaGetSymbolAddress((void**)&p_xhi,  g_xhi);
    cudaGetSymbolAddress((void**)&p_xlo,  g_xlo);
    cudaGetSymbolAddress((void**)&p_w1hi, g_w1hi);
    cudaGetSymbolAddress((void**)&p_w1lo, g_w1lo);
    cudaGetSymbolAddress((void**)&p_w2hi, g_w2hi);
    cudaGetSymbolAddress((void**)&p_w2lo, g_w2lo);
    cudaGetSymbolAddress((void**)&p_ghi,  g_ghi);
    cudaGetSymbolAddress((void**)&p_glo,  g_glo);

    cudaFuncSetAttribute(gemm_bf16x3, cudaFuncAttributeMaxDynamicSharedMemorySize, GSMEM);
    cudaFuncSetAttribute(scan_zgemm, cudaFuncAttributeMaxDynamicSharedMemorySize, GSMEM);

    // splits for GEMM operands
    split_bf16<<<(TOK * (size_t)HID) / 1024, 256>>>(x, p_xhi, p_xlo);
    split_bf16<<<((size_t)PQKVZ * HID) / 1024, 256>>>(W_qkvz, p_w1hi, p_w1lo);
    split_bf16<<<((size_t)HID * VALD) / 1024, 256>>>(W_out, p_w2hi, p_w2lo);

    // 1) qkv part of qkvz = x @ W_qkvz[0:8192]^T  (z columns deferred to fused kernel)
    gemm_bf16x3<<<dim3(TOK / 128, CONVD / 128), 256, GSMEM>>>(
        p_xhi, p_xlo, p_w1hi, p_w1lo, p_qkvz, TOK, CONVD, HID, PQKVZ);
    // 2) ba = x @ W_ba^T (SIMT, tiny)
    sgemm_nt<<<dim3(1, TOK / BM), 256>>>(x, W_ba, p_ba, TOK, 64, HID);
    // 3) conv + silu
    conv_silu_kernel<<<(TOK * (size_t)CONVD) / 256, 256>>>(p_qkvz, conv_w, p_conv);
    // 4) l2norm + gates
    prep_kernel<<<TOK, 512>>>(p_conv, p_ba, dt_bias, A_log, p_qn, p_kn, p_beta, p_g);
    // 5) fused: delta-rule scan (warps 0-7) + z-GEMM (warps 8-15, dynamic tiles)
    cudaMemsetAsync(p_ctr, 0, sizeof(int));
    scan_zgemm<<<148, 512, GSMEM>>>(p_qn, p_kn, p_conv, p_beta, p_g, p_core,
                                    p_xhi, p_xlo,
                                    p_w1hi + (size_t)CONVD * HID, p_w1lo + (size_t)CONVD * HID,
                                    p_qkvz);
    // 6) rmsnorm + gate -> bf16 hi/lo directly
    rmsnorm_gate_kernel<<<TOK, 256>>>(p_core, p_qkvz, norm_w, p_ghi, p_glo);
    // 7) out = gated @ W_out^T
    gemm_bf16x3<<<dim3(TOK / 128, HID / 128), 256, GSMEM>>>(
        p_ghi, p_glo, p_w2hi, p_w2lo, out, TOK, HID, VALD, HID);
}

// round 15
// speedup vs baseline: 1.1055x; 1.0370x over previous
#include <cuda_runtime.h>
#include <cuda_bf16.h>
#include <cstdint>

// ---------------- model dims ----------------
#define BATCH 2
#define SEQ   2048
#define TOK   (BATCH*SEQ)        // 4096
#define HID   2048
#define NK    16
#define NV    32
#define DK    128
#define DV    128
#define KEYD  2048               // NK*DK
#define VALD  4096               // NV*DV
#define CONVD 8192               // 2*KEYD + VALD
#define PQKVZ 12288              // 2*KEYD + 2*VALD
#define EPSF  1e-6f

// ---------------- scratch (device globals; no allocation) ----------------
__device__ float g_qkvz [(size_t)TOK * PQKVZ];
__device__ float g_ba   [(size_t)TOK * 64];
__device__ float g_conv [(size_t)TOK * CONVD];
__device__ float g_qn   [(size_t)TOK * KEYD];
__device__ float g_kn   [(size_t)TOK * KEYD];
__device__ float g_beta [(size_t)TOK * NV];
__device__ float g_gdec [(size_t)TOK * NV];
__device__ float g_core [(size_t)TOK * VALD];
// bf16 hi/lo split scratch
__device__ __nv_bfloat16 g_xhi [(size_t)TOK * HID];
__device__ __nv_bfloat16 g_xlo [(size_t)TOK * HID];
__device__ __nv_bfloat16 g_w1hi[(size_t)PQKVZ * HID];
__device__ __nv_bfloat16 g_w1lo[(size_t)PQKVZ * HID];
__device__ __nv_bfloat16 g_w2hi[(size_t)HID * VALD];
__device__ __nv_bfloat16 g_w2lo[(size_t)HID * VALD];
__device__ __nv_bfloat16 g_ghi [(size_t)TOK * VALD];
__device__ __nv_bfloat16 g_glo [(size_t)TOK * VALD];

// ---------------- helpers ----------------
__device__ __forceinline__ uint32_t smem_u32(const void* p) {
    uint32_t r;
    asm("{ .reg .u64 t; cvta.to.shared.u64 t, %1; cvt.u32.u64 %0, t; }" : "=r"(r) : "l"(p));
    return r;
}
__device__ __forceinline__ void cpasync16(uint32_t s, const void* g) {
    asm volatile("cp.async.cg.shared.global [%0], [%1], 16;" :: "r"(s), "l"(g));
}
__device__ __forceinline__ void cpasync4(uint32_t s, const void* g) {
    asm volatile("cp.async.ca.shared.global [%0], [%1], 4;" :: "r"(s), "l"(g));
}
__device__ __forceinline__ void ldmx4(uint32_t* r, uint32_t addr) {
    asm volatile("ldmatrix.sync.aligned.m8n8.x4.shared.b16 {%0,%1,%2,%3}, [%4];"
                 : "=r"(r[0]), "=r"(r[1]), "=r"(r[2]), "=r"(r[3]) : "r"(addr));
}
__device__ __forceinline__ void mma16816(float* c, const uint32_t* a, const uint32_t* b) {
    asm volatile(
        "mma.sync.aligned.m16n8k16.row.col.f32.bf16.bf16.f32 "
        "{%0,%1,%2,%3}, {%4,%5,%6,%7}, {%8,%9}, {%0,%1,%2,%3};"
        : "+f"(c[0]), "+f"(c[1]), "+f"(c[2]), "+f"(c[3])
        : "r"(a[0]), "r"(a[1]), "r"(a[2]), "r"(a[3]), "r"(b[0]), "r"(b[1]));
}
// f32x2 packed math
__device__ __forceinline__ unsigned long long pk2(float a, float b) {
    unsigned long long r; asm("mov.b64 %0, {%1, %2};" : "=l"(r) : "f"(a), "f"(b)); return r;
}
__device__ __forceinline__ unsigned long long fma2(unsigned long long a, unsigned long long b, unsigned long long c) {
    unsigned long long d; asm("fma.rn.f32x2 %0, %1, %2, %3;" : "=l"(d) : "l"(a), "l"(b), "l"(c)); return d;
}
__device__ __forceinline__ unsigned long long mul2(unsigned long long a, unsigned long long b) {
    unsigned long long d; asm("mul.rn.f32x2 %0, %1, %2;" : "=l"(d) : "l"(a), "l"(b)); return d;
}
__device__ __forceinline__ float hadd2(unsigned long long v) {
    float a, b; asm("mov.b64 {%0, %1}, %2;" : "=f"(a), "=f"(b) : "l"(v)); return a + b;
}

// ---------------- split fp32 -> bf16 hi/lo ----------------
__global__ __launch_bounds__(256) void split_bf16(const float* __restrict__ src,
                                                  __nv_bfloat16* __restrict__ hi,
                                                  __nv_bfloat16* __restrict__ lo) {
    size_t i = ((size_t)blockIdx.x * blockDim.x + threadIdx.x) * 4;
    float4 v = *(const float4*)(src + i);
    __nv_bfloat16 h0 = __float2bfloat16(v.x), h1 = __float2bfloat16(v.y);
    __nv_bfloat16 h2 = __float2bfloat16(v.z), h3 = __float2bfloat16(v.w);
    __nv_bfloat16 l0 = __float2bfloat16(v.x - __bfloat162float(h0));
    __nv_bfloat16 l1 = __float2bfloat16(v.y - __bfloat162float(h1));
    __nv_bfloat16 l2 = __float2bfloat16(v.z - __bfloat162float(h2));
    __nv_bfloat16 l3 = __float2bfloat16(v.w - __bfloat162float(h3));
    __nv_bfloat162* hp = (__nv_bfloat162*)(hi + i);
    __nv_bfloat162* lp = (__nv_bfloat162*)(lo + i);
    hp[0] = __nv_bfloat162(h0, h1); hp[1] = __nv_bfloat162(h2, h3);
    lp[0] = __nv_bfloat162(l0, l1); lp[1] = __nv_bfloat162(l2, l3);
}

// ---------------- mma.sync bf16x3 GEMM (NT): C[m,n(ldc)] = sum_k A[m,k]*B[n,k] ----------------
#define TSTRIDE 80
#define TILE_B  (128 * TSTRIDE)
#define STAGE_B (4 * TILE_B)
#define GSMEM   (2 * STAGE_B)

__global__ __launch_bounds__(256, 2)
void gemm_bf16x3(const __nv_bfloat16* __restrict__ Ah, const __nv_bfloat16* __restrict__ Al,
                 const __nv_bfloat16* __restrict__ Bh, const __nv_bfloat16* __restrict__ Bl,
                 float* __restrict__ C, int M, int N, int K, int ldc) {
    extern __shared__ __align__(16) char sm[];
    const uint32_t sb = smem_u32(sm);
    const int tid = threadIdx.x;
    const int lane = tid & 31, wid = tid >> 5;
    const int bm = blockIdx.x * 128, bn = blockIdx.y * 128;
    const int wm = (wid & 1) * 64, wn = (wid >> 1) * 32;
    const int grp = lane >> 2, qid = lane & 3;

    const uint32_t a_row = (uint32_t)(lane & 15);
    const uint32_t a_c16 = (uint32_t)((lane >> 4) * 16);
    const uint32_t b_row = (uint32_t)((lane & 7) + ((lane >> 4) & 1) * 8);
    const uint32_t b_c16 = (uint32_t)(((lane >> 3) & 1) * 16);

    float c[4][4][4];
    #pragma unroll
    for (int i = 0; i < 4; i++)
        #pragma unroll
        for (int j = 0; j < 4; j++)
            #pragma unroll
            for (int r = 0; r < 4; r++) c[i][j][r] = 0.f;

    const int niter = K >> 5;

    auto issue = [&](int kblk, int buf) {
        const int k0 = kblk * 32;
        #pragma unroll
        for (int i = 0; i < 2; i++) {
            int chunk = tid + i * 256;
            int row = chunk >> 2, c16 = chunk & 3;
            size_t ga = (size_t)(bm + row) * K + k0 + c16 * 8;
            size_t gb = (size_t)(bn + row) * K + k0 + c16 * 8;
            uint32_t so = sb + buf * STAGE_B + row * TSTRIDE + c16 * 16;
            cpasync16(so,              Ah + ga);
            cpasync16(so + TILE_B,     Al + ga);
            cpasync16(so + 2 * TILE_B, Bh + gb);
            cpasync16(so + 3 * TILE_B, Bl + gb);
        }
    };

    issue(0, 0);
    asm volatile("cp.async.commit_group;" ::: "memory");
    issue(1, 1);
    asm volatile("cp.async.commit_group;" ::: "memory");

    for (int it = 0; it < niter; it++) {
        asm volatile("cp.async.wait_group 1;" ::: "memory");
        __syncthreads();
        const int buf = it & 1;
        const uint32_t base = sb + buf * STAGE_B;

        #pragma unroll
        for (int ks = 0; ks < 2; ks++) {
            const uint32_t koff = ks * 32;
            const uint32_t abase = base + (uint32_t)(wm + a_row) * TSTRIDE + koff + a_c16;
            const uint32_t bbase = base + 2 * TILE_B + (uint32_t)(wn + b_row) * TSTRIDE + koff + b_c16;
            uint32_t ah[4][4], bh[2][4];
            #pragma unroll
            for (int i = 0; i < 4; i++) ldmx4(ah[i], abase + (uint32_t)(i * 16) * TSTRIDE);
            #pragma unroll
            for (int J = 0; J < 2; J++) ldmx4(bh[J], bbase + (uint32_t)(J * 16) * TSTRIDE);
            #pragma unroll
            for (int i = 0; i < 4; i++)
                #pragma unroll
                for (int j = 0; j < 4; j++) mma16816(c[i][j], ah[i], &bh[j >> 1][(j & 1) * 2]);
            {
                uint32_t al[4][4];
                #pragma unroll
                for (int i = 0; i < 4; i++) ldmx4(al[i], abase + TILE_B + (uint32_t)(i * 16) * TSTRIDE);
                #pragma unroll
                for (int i = 0; i < 4; i++)
                    #pragma unroll
                    for (int j = 0; j < 4; j++) mma16816(c[i][j], al[i], &bh[j >> 1][(j & 1) * 2]);
            }
            {
                uint32_t bl[2][4];
                #pragma unroll
                for (int J = 0; J < 2; J++) ldmx4(bl[J], bbase + TILE_B + (uint32_t)(J * 16) * TSTRIDE);
                #pragma unroll
                for (int i = 0; i < 4; i++)
                    #pragma unroll
                    for (int j = 0; j < 4; j++) mma16816(c[i][j], ah[i], &bl[j >> 1][(j & 1) * 2]);
            }
        }
        __syncthreads();
        if (it + 2 < niter) issue(it + 2, buf);
        asm volatile("cp.async.commit_group;" ::: "memory");
    }

    #pragma unroll
    for (int i = 0; i < 4; i++) {
        const int row0 = bm + wm + i * 16 + grp;
        #pragma unroll
        for (int j = 0; j < 4; j++) {
            const int col = bn + wn + j * 8 + qid * 2;
            float2 v01 = make_float2(c[i][j][0], c[i][j][1]);
            float2 v23 = make_float2(c[i][j][2], c[i][j][3]);
            *(float2*)(C + (size_t)row0 * ldc + col)       = v01;
            *(float2*)(C + (size_t)(row0 + 8) * ldc + col) = v23;
        }
    }
}

// ---------------- SIMT SGEMM (NT) for tiny ba GEMM ----------------
#define BM 128
#define BN 128
#define BKK 16
__global__ __launch_bounds__(256) void sgemm_nt(const float* __restrict__ A,
                                                const float* __restrict__ B,
                                                float* __restrict__ C,
                                                int M, int N, int K) {
    __shared__ float As[BKK][BM];
    __shared__ float Bs[BKK][BN];
    const int tid = threadIdx.x;
    const int bm = blockIdx.y * BM;
    const int bn = blockIdx.x * BN;
    const int tx = tid & 15;
    const int ty = tid >> 4;
    const int lrow = tid >> 2;
    const int lk4 = (tid & 3) * 4;

    float acc[8][8];
    #pragma unroll
    for (int i = 0; i < 8; i++)
        #pragma unroll
        for (int j = 0; j < 8; j++) acc[i][j] = 0.f;

    for (int k0 = 0; k0 < K; k0 += BKK) {
        #pragma unroll
        for (int it = 0; it < 2; it++) {
            int row = lrow + it * 64;
            float4 v = *(const float4*)(A + (size_t)(bm + row) * K + k0 + lk4);
            As[lk4 + 0][row] = v.x; As[lk4 + 1][row] = v.y;
            As[lk4 + 2][row] = v.z; As[lk4 + 3][row] = v.w;
        }
        #pragma unroll
        for (int it = 0; it < 2; it++) {
            int row = lrow + it * 64;
            int gn = bn + row;
            float4 v = make_float4(0.f, 0.f, 0.f, 0.f);
            if (gn < N) v = *(const float4*)(B + (size_t)gn * K + k0 + lk4);
            Bs[lk4 + 0][row] = v.x; Bs[lk4 + 1][row] = v.y;
            Bs[lk4 + 2][row] = v.z; Bs[lk4 + 3][row] = v.w;
        }
        __syncthreads();
        #pragma unroll
        for (int kk = 0; kk < BKK; kk++) {
            float ar[8], br[8];
            #pragma unroll
            for (int i = 0; i < 8; i++) ar[i] = As[kk][ty * 8 + i];
            #pragma unroll
            for (int j = 0; j < 8; j++) br[j] = Bs[kk][tx * 8 + j];
            #pragma unroll
            for (int i = 0; i < 8; i++)
                #pragma unroll
                for (int j = 0; j < 8; j++)
                    acc[i][j] = fmaf(ar[i], br[j], acc[i][j]);
        }
        __syncthreads();
    }
    #pragma unroll
    for (int i = 0; i < 8; i++) {
        int gm = bm + ty * 8 + i;
        #pragma unroll
        for (int j = 0; j < 8; j++) {
            int gn = bn + tx * 8 + j;
            if (gn < N) C[(size_t)gm * N + gn] = acc[i][j];
        }
    }
}

// ---------------- depthwise causal conv1d (K=4) + SiLU ----------------
__global__ void conv_silu_kernel(const float* __restrict__ qkvz,
                                 const float* __restrict__ cw,
                                 float* __restrict__ out) {
    size_t idx = (size_t)blockIdx.x * blockDim.x + threadIdx.x;
    int c = (int)(idx & (CONVD - 1));
    size_t t = idx >> 13;
    int s = (int)(t & (SEQ - 1));
    size_t b = t >> 11;
    const float* base = qkvz + (b * SEQ) * (size_t)PQKVZ + c;
    float w0 = cw[c * 4 + 0], w1 = cw[c * 4 + 1], w2 = cw[c * 4 + 2], w3 = cw[c * 4 + 3];
    float acc = w3 * base[(size_t)s * PQKVZ];
    if (s >= 1) acc = fmaf(w2, base[(size_t)(s - 1) * PQKVZ], acc);
    if (s >= 2) acc = fmaf(w1, base[(size_t)(s - 2) * PQKVZ], acc);
    if (s >= 3) acc = fmaf(w0, base[(size_t)(s - 3) * PQKVZ], acc);
    out[idx] = acc / (1.f + expf(-acc));
}

// ---------------- l2norm(q,k) + gates ----------------
__global__ __launch_bounds__(512) void prep_kernel(const float* __restrict__ conv,
                                                   const float* __restrict__ ba,
                                                   const float* __restrict__ dt_bias,
                                                   const float* __restrict__ A_log,
                                                   float* __restrict__ qn,
                                                   float* __restrict__ kn,
                                                   float* __restrict__ beta,
                                                   float* __restrict__ gdec) {
    size_t t = blockIdx.x;
    int w = threadIdx.x >> 5;
    int l = threadIdx.x & 31;
    const float* cq = conv + t * CONVD + w * DK;
    const float* ck = conv + t * CONVD + KEYD + w * DK;
    float qv[4], kv[4];
    float sq = 0.f, sk = 0.f;
    #pragma unroll
    for (int i = 0; i < 4; i++) {
        qv[i] = cq[l + 32 * i]; sq = fmaf(qv[i], qv[i], sq);
        kv[i] = ck[l + 32 * i]; sk = fmaf(kv[i], kv[i], sk);
    }
    #pragma unroll
    for (int o = 16; o; o >>= 1) {
        sq += __shfl_xor_sync(0xffffffffu, sq, o);
        sk += __shfl_xor_sync(0xffffffffu, sk, o);
    }
    float rq = rsqrtf(sq + EPSF), rk = rsqrtf(sk + EPSF);
    #pragma unroll
    for (int i = 0; i < 4; i++) {
        qn[(t * NK + w) * DK + l + 32 * i] = qv[i] * rq;
        kn[(t * NK + w) * DK + l + 32 * i] = kv[i] * rk;
    }
    if (threadIdx.x < NV) {
        int h = threadIdx.x;
        float bv = ba[t * 64 + h];
        float av = ba[t * 64 + NV + h];
        beta[t * NV + h] = 1.f / (1.f + expf(-bv));
        float xx = av + dt_bias[h];
        float sp = (xx > 20.f) ? xx : log1pf(expf(xx));
        gdec[t * NV + h] = expf(-expf(A_log[h]) * sp);
    }
}

// ---------------- gated delta-rule scan v5 (standalone; best measured) ----------------
#define SCH   8
#define KROW  144   // 4 quarters * 36 floats
__global__ __launch_bounds__(256) void scan_kernel(const float* __restrict__ qn,
                                                   const float* __restrict__ kn,
                                                   const float* __restrict__ conv,
                                                   const float* __restrict__ beta,
                                                   const float* __restrict__ gdec,
                                                   float* __restrict__ core) {
    const int h = blockIdx.x;        // value head
    const int dv0 = blockIdx.y * 64; // DV half
    const int b = blockIdx.z;
    const int nk = h >> 1;
    const int tid = threadIdx.x;
    const int col = tid >> 2;        // local DV col 0..63
    const int quarter = tid & 3;     // DK quarter
    __shared__ float ksm[2][SCH][KROW];
    __shared__ float qsm[2][SCH][KROW];
    __shared__ float vsm[2][SCH][64];
    __shared__ float gsm[2][SCH], bsm[2][SCH];

    unsigned long long st[16];
    #pragma unroll
    for (int j = 0; j < 16; j++) st[j] = 0ull;

    const size_t tbase = (size_t)b * SEQ;
    const int krow_t = tid >> 5, kln = tid & 31;
    const int kqoff = (kln >> 3) * 36 + (kln & 7) * 4;

    auto issue = [&](int blk, int buf) {
        const size_t t0 = tbase + (size_t)blk * SCH;
        cpasync16(smem_u32(&ksm[buf][krow_t][kqoff]), kn + ((t0 + krow_t) * NK + nk) * DK + kln * 4);
        cpasync16(smem_u32(&qsm[buf][krow_t][kqoff]), qn + ((t0 + krow_t) * NK + nk) * DK + kln * 4);
        if (tid < 128) {
            int vr = tid >> 4, vc = (tid & 15) * 4;
            cpasync16(smem_u32(&vsm[buf][vr][vc]),
                      conv + (t0 + vr) * CONVD + 2 * KEYD + h * DV + dv0 + vc);
        } else if (tid < 128 + SCH) {
            cpasync4(smem_u32(&gsm[buf][tid - 128]), gdec + (t0 + tid - 128) * NV + h);
        } else if (tid < 128 + 2 * SCH) {
            cpasync4(smem_u32(&bsm[buf][tid - 128 - SCH]), beta + (t0 + tid - 128 - SCH) * NV + h);
        }
    };

    issue(0, 0);
    asm volatile("cp.async.commit_group;" ::: "memory");
    issue(1, 1);
    asm volatile("cp.async.commit_group;" ::: "memory");

    const int nblk = SEQ / SCH;
    for (int blk = 0; blk < nblk; blk++) {
        const int buf = blk & 1;
        asm volatile("cp.async.wait_group 1;" ::: "memory");
        __syncthreads();

        #pragma unroll
        for (int i = 0; i < SCH; i++) {
            const ulonglong2* kk = (const ulonglong2*)&ksm[buf][i][quarter * 36];
            const ulonglong2* qq = (const ulonglong2*)&qsm[buf][i][quarter * 36];
            float vt = vsm[buf][i][col];
            float ge = gsm[buf][i];
            float bt = bsm[buf][i];

            unsigned long long a0 = 0ull, a1 = 0ull;
            #pragma unroll
            for (int j = 0; j < 8; j++) {
                ulonglong2 kj = kk[j];
                a0 = fma2(kj.x, st[2 * j + 0], a0);
                a1 = fma2(kj.y, st[2 * j + 1], a1);
            }
            float kvd = hadd2(a0) + hadd2(a1);
            kvd += __shfl_xor_sync(0xffffffffu, kvd, 1);
            kvd += __shfl_xor_sync(0xffffffffu, kvd, 2);
            float delta = bt * (vt - ge * kvd);
            unsigned long long ge2 = pk2(ge, ge);
            unsigned long long d2 = pk2(delta, delta);

            unsigned long long o0 = 0ull, o1 = 0ull;
            #pragma unroll
            for (int j = 0; j < 8; j++) {
                ulonglong2 kj = kk[j], qj = qq[j];
                st[2 * j + 0] = fma2(ge2, st[2 * j + 0], mul2(kj.x, d2));
                o0 = fma2(qj.x, st[2 * j + 0], o0);
                st[2 * j + 1] = fma2(ge2, st[2 * j + 1], mul2(kj.y, d2));
                o1 = fma2(qj.y, st[2 * j + 1], o1);
            }
            float o = hadd2(o0) + hadd2(o1);
            o += __shfl_xor_sync(0xffffffffu, o, 1);
            o += __shfl_xor_sync(0xffffffffu, o, 2);
            if (quarter == 0)
                core[(tbase + (size_t)blk * SCH + i) * VALD + h * DV + dv0 + col] = o;
        }

        __syncthreads();
        if (blk + 2 < nblk) issue(blk + 2, buf);
        asm volatile("cp.async.commit_group;" ::: "memory");
    }
}

// ---------------- RMSNorm(1+w) + silu(z) gate -> bf16 hi/lo ----------------
__global__ __launch_bounds__(256) void rmsnorm_gate_kernel(const float* __restrict__ core,
                                                           const float* __restrict__ qkvz,
                                                           const float* __restrict__ norm_w,
                                                           __nv_bfloat16* __restrict__ ghi,
                                                           __nv_bfloat16* __restrict__ glo) {
    size_t t = blockIdx.x;
    __shared__ float red[8];
    __shared__ float s_scale;
    const float* row = core + t * VALD;
    const float* zrow = qkvz + t * PQKVZ + 2 * KEYD + VALD;
    float ss = 0.f;
    for (int c = threadIdx.x; c < VALD; c += 256) { float v = row[c]; ss = fmaf(v, v, ss); }
    #pragma unroll
    for (int o = 16; o; o >>= 1) ss += __shfl_xor_sync(0xffffffffu, ss, o);
    if ((threadIdx.x & 31) == 0) red[threadIdx.x >> 5] = ss;
    __syncthreads();
    if (threadIdx.x == 0) {
        float tot = 0.f;
        #pragma unroll
        for (int i = 0; i < 8; i++) tot += red[i];
        s_scale = rsqrtf(tot * (1.f / VALD) + EPSF);
    }
    __syncthreads();
    float sc = s_scale;
    for (int c = threadIdx.x; c < VALD; c += 256) {
        float z = zrow[c];
        float sz = z / (1.f + expf(-z));
        float val = row[c] * sc * (1.f + norm_w[c]) * sz;
        __nv_bfloat16 hv = __float2bfloat16(val);
        ghi[t * VALD + c] = hv;
        glo[t * VALD + c] = __float2bfloat16(val - __bfloat162float(hv));
    }
}

// ---------------- launch (multi-stream capture graph, correct fork protocol) ----------------
extern "C" void kernel_launch(void* const* d_in, const int* in_sizes, int n_in,
                              void* d_out, int out_size) {
    const float* x       = (const float*)d_in[0];
    const float* W_qkvz  = (const float*)d_in[1];
    const float* W_ba    = (const float*)d_in[2];
    const float* conv_w  = (const float*)d_in[3];
    const float* dt_bias = (const float*)d_in[4];
    const float* A_log   = (const float*)d_in[5];
    const float* norm_w  = (const float*)d_in[6];
    const float* W_out   = (const float*)d_in[7];
    float* out = (float*)d_out;

    float *p_qkvz, *p_ba, *p_conv, *p_qn, *p_kn, *p_beta, *p_g, *p_core;
    __nv_bfloat16 *p_xhi, *p_xlo, *p_w1hi, *p_w1lo, *p_w2hi, *p_w2lo, *p_ghi, *p_glo;
    cudaGetSymbolAddress((void**)&p_qkvz,  g_qkvz);
    cudaGetSymbolAddress((void**)&p_ba,    g_ba);
    cudaGetSymbolAddress((void**)&p_conv,  g_conv);
    cudaGetSymbolAddress((void**)&p_qn,    g_qn);
    cudaGetSymbolAddress((void**)&p_kn,    g_kn);
    cudaGetSymbolAddress((void**)&p_beta,  g_beta);
    cudaGetSymbolAddress((void**)&p_g,     g_gdec);
    cudaGetSymbolAddress((void**)&p_core,  g_core);
    cudaGetSymbolAddress((void**)&p_xhi,  g_xhi);
    cudaGetSymbolAddress((void**)&p_xlo,  g_xlo);
    cudaGetSymbolAddress((void**)&p_w1hi, g_w1hi);
    cudaGetSymbolAddress((void**)&p_w1lo, g_w1lo);
    cudaGetSymbolAddress((void**)&p_w2hi, g_w2hi);
    cudaGetSymbolAddress((void**)&p_w2lo, g_w2lo);
    cudaGetSymbolAddress((void**)&p_ghi,  g_ghi);
    cudaGetSymbolAddress((void**)&p_glo,  g_glo);

    cudaFuncSetAttribute(gemm_bf16x3, cudaFuncAttributeMaxDynamicSharedMemorySize, GSMEM);

    // side stream + events (host objects; not stream operations)
    cudaStream_t s2;
    cudaStreamCreateWithFlags(&s2, cudaStreamNonBlocking);
    cudaEvent_t e0, e1, e2, e3;
    cudaEventCreateWithFlags(&e0, cudaEventDisableTiming);
    cudaEventCreateWithFlags(&e1, cudaEventDisableTiming);
    cudaEventCreateWithFlags(&e2, cudaEventDisableTiming);
    cudaEventCreateWithFlags(&e3, cudaEventDisableTiming);

    // --- fork: s2 joins the capture BEFORE doing any work ---
    cudaEventRecord(e0, 0);
    cudaStreamWaitEvent(s2, e0, 0);

    // --- stream2: ba GEMM (depends only on inputs) ---
    sgemm_nt<<<dim3(1, TOK / BM), 256, 0, s2>>>(x, W_ba, p_ba, TOK, 64, HID);
    cudaEventRecord(e3, s2);

    // --- stream1 (default): splits + qkv GEMM ---
    split_bf16<<<(TOK * (size_t)HID) / 1024, 256>>>(x, p_xhi, p_xlo);
    split_bf16<<<((size_t)PQKVZ * HID) / 1024, 256>>>(W_qkvz, p_w1hi, p_w1lo);
    split_bf16<<<((size_t)HID * VALD) / 1024, 256>>>(W_out, p_w2hi, p_w2lo);
    gemm_bf16x3<<<dim3(TOK / 128, CONVD / 128), 256, GSMEM>>>(
        p_xhi, p_xlo, p_w1hi, p_w1lo, p_qkvz, TOK, CONVD, HID, PQKVZ);
    cudaEventRecord(e1, 0);

    // --- stream2: z-GEMM overlaps conv/prep/scan on stream1 ---
    cudaStreamWaitEvent(s2, e1, 0);
    gemm_bf16x3<<<dim3(TOK / 128, VALD / 128), 256, GSMEM, s2>>>(
        p_xhi, p_xlo,
        p_w1hi + (size_t)CONVD * HID, p_w1lo + (size_t)CONVD * HID,
        p_qkvz + 2 * KEYD + VALD, TOK, VALD, HID, PQKVZ);
    cudaEventRecord(e2, s2);

    // --- stream1: conv -> prep -> scan ---
    conv_silu_kernel<<<(TOK * (size_t)CONVD) / 256, 256>>>(p_qkvz, conv_w, p_conv);
    cudaStreamWaitEvent(0, e3, 0);   // prep needs ba
    prep_kernel<<<TOK, 512>>>(p_conv, p_ba, dt_bias, A_log, p_qn, p_kn, p_beta, p_g);
    scan_kernel<<<dim3(NV, 2, BATCH), 256>>>(p_qn, p_kn, p_conv, p_beta, p_g, p_core);

    // --- join: rmsnorm needs z columns; merges s2 back into capture origin ---
    cudaStreamWaitEvent(0, e2, 0);
    rmsnorm_gate_kernel<<<TOK, 256>>>(p_core, p_qkvz, norm_w, p_ghi, p_glo);
    gemm_bf16x3<<<dim3(TOK / 128, HID / 128), 256, GSMEM>>>(
        p_ghi, p_glo, p_w2hi, p_w2lo, out, TOK, HID, VALD, HID);
}

// round 16
// speedup vs baseline: 1.1088x; 1.0030x over previous
#include <cuda_runtime.h>
#include <cuda_bf16.h>
#include <cstdint>

// ---------------- model dims ----------------
#define BATCH 2
#define SEQ   2048
#define TOK   (BATCH*SEQ)        // 4096
#define HID   2048
#define NK    16
#define NV    32
#define DK    128
#define DV    128
#define KEYD  2048               // NK*DK
#define VALD  4096               // NV*DV
#define CONVD 8192               // 2*KEYD + VALD
#define PQKVZ 12288              // 2*KEYD + 2*VALD
#define EPSF  1e-6f

// ---------------- scratch (device globals; no allocation) ----------------
__device__ float g_qkvz [(size_t)TOK * PQKVZ];
__device__ float g_ba   [(size_t)TOK * 64];
__device__ float g_conv [(size_t)TOK * CONVD];
__device__ float g_qn   [(size_t)TOK * KEYD];
__device__ float g_kn   [(size_t)TOK * KEYD];
__device__ float g_beta [(size_t)TOK * NV];
__device__ float g_gdec [(size_t)TOK * NV];
__device__ float g_core [(size_t)TOK * VALD];
// bf16 hi/lo split scratch
__device__ __nv_bfloat16 g_xhi [(size_t)TOK * HID];
__device__ __nv_bfloat16 g_xlo [(size_t)TOK * HID];
__device__ __nv_bfloat16 g_w1hi[(size_t)PQKVZ * HID];
__device__ __nv_bfloat16 g_w1lo[(size_t)PQKVZ * HID];
__device__ __nv_bfloat16 g_w2hi[(size_t)HID * VALD];
__device__ __nv_bfloat16 g_w2lo[(size_t)HID * VALD];
__device__ __nv_bfloat16 g_ghi [(size_t)TOK * VALD];
__device__ __nv_bfloat16 g_glo [(size_t)TOK * VALD];

// ---------------- helpers ----------------
__device__ __forceinline__ uint32_t smem_u32(const void* p) {
    uint32_t r;
    asm("{ .reg .u64 t; cvta.to.shared.u64 t, %1; cvt.u32.u64 %0, t; }" : "=r"(r) : "l"(p));
    return r;
}
__device__ __forceinline__ void cpasync16(uint32_t s, const void* g) {
    asm volatile("cp.async.cg.shared.global [%0], [%1], 16;" :: "r"(s), "l"(g));
}
__device__ __forceinline__ void cpasync4(uint32_t s, const void* g) {
    asm volatile("cp.async.ca.shared.global [%0], [%1], 4;" :: "r"(s), "l"(g));
}
__device__ __forceinline__ void ldmx4(uint32_t* r, uint32_t addr) {
    asm volatile("ldmatrix.sync.aligned.m8n8.x4.shared.b16 {%0,%1,%2,%3}, [%4];"
                 : "=r"(r[0]), "=r"(r[1]), "=r"(r[2]), "=r"(r[3]) : "r"(addr));
}
__device__ __forceinline__ void mma16816(float* c, const uint32_t* a, const uint32_t* b) {
    asm volatile(
        "mma.sync.aligned.m16n8k16.row.col.f32.bf16.bf16.f32 "
        "{%0,%1,%2,%3}, {%4,%5,%6,%7}, {%8,%9}, {%0,%1,%2,%3};"
        : "+f"(c[0]), "+f"(c[1]), "+f"(c[2]), "+f"(c[3])
        : "r"(a[0]), "r"(a[1]), "r"(a[2]), "r"(a[3]), "r"(b[0]), "r"(b[1]));
}
// f32x2 packed math
__device__ __forceinline__ unsigned long long pk2(float a, float b) {
    unsigned long long r; asm("mov.b64 %0, {%1, %2};" : "=l"(r) : "f"(a), "f"(b)); return r;
}
__device__ __forceinline__ unsigned long long fma2(unsigned long long a, unsigned long long b, unsigned long long c) {
    unsigned long long d; asm("fma.rn.f32x2 %0, %1, %2, %3;" : "=l"(d) : "l"(a), "l"(b), "l"(c)); return d;
}
__device__ __forceinline__ unsigned long long mul2(unsigned long long a, unsigned long long b) {
    unsigned long long d; asm("mul.rn.f32x2 %0, %1, %2;" : "=l"(d) : "l"(a), "l"(b)); return d;
}
__device__ __forceinline__ float hadd2(unsigned long long v) {
    float a, b; asm("mov.b64 {%0, %1}, %2;" : "=f"(a), "=f"(b) : "l"(v)); return a + b;
}

// ---------------- split fp32 -> bf16 hi/lo ----------------
__global__ __launch_bounds__(256) void split_bf16(const float* __restrict__ src,
                                                  __nv_bfloat16* __restrict__ hi,
                                                  __nv_bfloat16* __restrict__ lo) {
    size_t i = ((size_t)blockIdx.x * blockDim.x + threadIdx.x) * 4;
    float4 v = *(const float4*)(src + i);
    __nv_bfloat16 h0 = __float2bfloat16(v.x), h1 = __float2bfloat16(v.y);
    __nv_bfloat16 h2 = __float2bfloat16(v.z), h3 = __float2bfloat16(v.w);
    __nv_bfloat16 l0 = __float2bfloat16(v.x - __bfloat162float(h0));
    __nv_bfloat16 l1 = __float2bfloat16(v.y - __bfloat162float(h1));
    __nv_bfloat16 l2 = __float2bfloat16(v.z - __bfloat162float(h2));
    __nv_bfloat16 l3 = __float2bfloat16(v.w - __bfloat162float(h3));
    __nv_bfloat162* hp = (__nv_bfloat162*)(hi + i);
    __nv_bfloat162* lp = (__nv_bfloat162*)(lo + i);
    hp[0] = __nv_bfloat162(h0, h1); hp[1] = __nv_bfloat162(h2, h3);
    lp[0] = __nv_bfloat162(l0, l1); lp[1] = __nv_bfloat162(l2, l3);
}

// ---------------- mma.sync bf16x3 GEMM (NT): C[m,n(ldc)] = sum_k A[m,k]*B[n,k] ----------------
#define TSTRIDE 80
#define TILE_B  (128 * TSTRIDE)
#define STAGE_B (4 * TILE_B)
#define GSMEM   (2 * STAGE_B)

__global__ __launch_bounds__(256, 2)
void gemm_bf16x3(const __nv_bfloat16* __restrict__ Ah, const __nv_bfloat16* __restrict__ Al,
                 const __nv_bfloat16* __restrict__ Bh, const __nv_bfloat16* __restrict__ Bl,
                 float* __restrict__ C, int M, int N, int K, int ldc) {
    extern __shared__ __align__(16) char sm[];
    const uint32_t sb = smem_u32(sm);
    const int tid = threadIdx.x;
    const int lane = tid & 31, wid = tid >> 5;
    const int bm = blockIdx.x * 128, bn = blockIdx.y * 128;
    const int wm = (wid & 1) * 64, wn = (wid >> 1) * 32;
    const int grp = lane >> 2, qid = lane & 3;

    const uint32_t a_row = (uint32_t)(lane & 15);
    const uint32_t a_c16 = (uint32_t)((lane >> 4) * 16);
    const uint32_t b_row = (uint32_t)((lane & 7) + ((lane >> 4) & 1) * 8);
    const uint32_t b_c16 = (uint32_t)(((lane >> 3) & 1) * 16);

    float c[4][4][4];
    #pragma unroll
    for (int i = 0; i < 4; i++)
        #pragma unroll
        for (int j = 0; j < 4; j++)
            #pragma unroll
            for (int r = 0; r < 4; r++) c[i][j][r] = 0.f;

    const int niter = K >> 5;

    auto issue = [&](int kblk, int buf) {
        const int k0 = kblk * 32;
        #pragma unroll
        for (int i = 0; i < 2; i++) {
            int chunk = tid + i * 256;
            int row = chunk >> 2, c16 = chunk & 3;
            size_t ga = (size_t)(bm + row) * K + k0 + c16 * 8;
            size_t gb = (size_t)(bn + row) * K + k0 + c16 * 8;
            uint32_t so = sb + buf * STAGE_B + row * TSTRIDE + c16 * 16;
            cpasync16(so,              Ah + ga);
            cpasync16(so + TILE_B,     Al + ga);
            cpasync16(so + 2 * TILE_B, Bh + gb);
            cpasync16(so + 3 * TILE_B, Bl + gb);
        }
    };

    issue(0, 0);
    asm volatile("cp.async.commit_group;" ::: "memory");
    issue(1, 1);
    asm volatile("cp.async.commit_group;" ::: "memory");

    for (int it = 0; it < niter; it++) {
        asm volatile("cp.async.wait_group 1;" ::: "memory");
        __syncthreads();
        const int buf = it & 1;
        const uint32_t base = sb + buf * STAGE_B;

        #pragma unroll
        for (int ks = 0; ks < 2; ks++) {
            const uint32_t koff = ks * 32;
            const uint32_t abase = base + (uint32_t)(wm + a_row) * TSTRIDE + koff + a_c16;
            const uint32_t bbase = base + 2 * TILE_B + (uint32_t)(wn + b_row) * TSTRIDE + koff + b_c16;
            uint32_t ah[4][4], bh[2][4];
            #pragma unroll
            for (int i = 0; i < 4; i++) ldmx4(ah[i], abase + (uint32_t)(i * 16) * TSTRIDE);
            #pragma unroll
            for (int J = 0; J < 2; J++) ldmx4(bh[J], bbase + (uint32_t)(J * 16) * TSTRIDE);
            #pragma unroll
            for (int i = 0; i < 4; i++)
                #pragma unroll
                for (int j = 0; j < 4; j++) mma16816(c[i][j], ah[i], &bh[j >> 1][(j & 1) * 2]);
            {
                uint32_t al[4][4];
                #pragma unroll
                for (int i = 0; i < 4; i++) ldmx4(al[i], abase + TILE_B + (uint32_t)(i * 16) * TSTRIDE);
                #pragma unroll
                for (int i = 0; i < 4; i++)
                    #pragma unroll
                    for (int j = 0; j < 4; j++) mma16816(c[i][j], al[i], &bh[j >> 1][(j & 1) * 2]);
            }
            {
                uint32_t bl[2][4];
                #pragma unroll
                for (int J = 0; J < 2; J++) ldmx4(bl[J], bbase + TILE_B + (uint32_t)(J * 16) * TSTRIDE);
                #pragma unroll
                for (int i = 0; i < 4; i++)
                    #pragma unroll
                    for (int j = 0; j < 4; j++) mma16816(c[i][j], ah[i], &bl[j >> 1][(j & 1) * 2]);
            }
        }
        __syncthreads();
        if (it + 2 < niter) issue(it + 2, buf);
        asm volatile("cp.async.commit_group;" ::: "memory");
    }

    #pragma unroll
    for (int i = 0; i < 4; i++) {
        const int row0 = bm + wm + i * 16 + grp;
        #pragma unroll
        for (int j = 0; j < 4; j++) {
            const int col = bn + wn + j * 8 + qid * 2;
            float2 v01 = make_float2(c[i][j][0], c[i][j][1]);
            float2 v23 = make_float2(c[i][j][2], c[i][j][3]);
            *(float2*)(C + (size_t)row0 * ldc + col)       = v01;
            *(float2*)(C + (size_t)(row0 + 8) * ldc + col) = v23;
        }
    }
}

// ---------------- SIMT SGEMM (NT) for tiny ba GEMM ----------------
#define BM 128
#define BN 128
#define BKK 16
__global__ __launch_bounds__(256) void sgemm_nt(const float* __restrict__ A,
                                                const float* __restrict__ B,
                                                float* __restrict__ C,
                                                int M, int N, int K) {
    __shared__ float As[BKK][BM];
    __shared__ float Bs[BKK][BN];
    const int tid = threadIdx.x;
    const int bm = blockIdx.y * BM;
    const int bn = blockIdx.x * BN;
    const int tx = tid & 15;
    const int ty = tid >> 4;
    const int lrow = tid >> 2;
    const int lk4 = (tid & 3) * 4;

    float acc[8][8];
    #pragma unroll
    for (int i = 0; i < 8; i++)
        #pragma unroll
        for (int j = 0; j < 8; j++) acc[i][j] = 0.f;

    for (int k0 = 0; k0 < K; k0 += BKK) {
        #pragma unroll
        for (int it = 0; it < 2; it++) {
            int row = lrow + it * 64;
            float4 v = *(const float4*)(A + (size_t)(bm + row) * K + k0 + lk4);
            As[lk4 + 0][row] = v.x; As[lk4 + 1][row] = v.y;
            As[lk4 + 2][row] = v.z; As[lk4 + 3][row] = v.w;
        }
        #pragma unroll
        for (int it = 0; it < 2; it++) {
            int row = lrow + it * 64;
            int gn = bn + row;
            float4 v = make_float4(0.f, 0.f, 0.f, 0.f);
            if (gn < N) v = *(const float4*)(B + (size_t)gn * K + k0 + lk4);
            Bs[lk4 + 0][row] = v.x; Bs[lk4 + 1][row] = v.y;
            Bs[lk4 + 2][row] = v.z; Bs[lk4 + 3][row] = v.w;
        }
        __syncthreads();
        #pragma unroll
        for (int kk = 0; kk < BKK; kk++) {
            float ar[8], br[8];
            #pragma unroll
            for (int i = 0; i < 8; i++) ar[i] = As[kk][ty * 8 + i];
            #pragma unroll
            for (int j = 0; j < 8; j++) br[j] = Bs[kk][tx * 8 + j];
            #pragma unroll
            for (int i = 0; i < 8; i++)
                #pragma unroll
                for (int j = 0; j < 8; j++)
                    acc[i][j] = fmaf(ar[i], br[j], acc[i][j]);
        }
        __syncthreads();
    }
    #pragma unroll
    for (int i = 0; i < 8; i++) {
        int gm = bm + ty * 8 + i;
        #pragma unroll
        for (int j = 0; j < 8; j++) {
            int gn = bn + tx * 8 + j;
            if (gn < N) C[(size_t)gm * N + gn] = acc[i][j];
        }
    }
}

// ---------------- depthwise causal conv1d (K=4) + SiLU, channel range ----------------
// Processes 4096 channels starting at c0. idx covers TOK*4096 elements.
__global__ void conv_silu_kernel(const float* __restrict__ qkvz,
                                 const float* __restrict__ cw,
                                 float* __restrict__ out, int c0) {
    size_t idx = (size_t)blockIdx.x * blockDim.x + threadIdx.x;
    int c = c0 + (int)(idx & 4095);
    size_t t = idx >> 12;
    int s = (int)(t & (SEQ - 1));
    size_t b = t >> 11;
    const float* base = qkvz + (b * SEQ) * (size_t)PQKVZ + c;
    float w0 = cw[c * 4 + 0], w1 = cw[c * 4 + 1], w2 = cw[c * 4 + 2], w3 = cw[c * 4 + 3];
    float acc = w3 * base[(size_t)s * PQKVZ];
    if (s >= 1) acc = fmaf(w2, base[(size_t)(s - 1) * PQKVZ], acc);
    if (s >= 2) acc = fmaf(w1, base[(size_t)(s - 2) * PQKVZ], acc);
    if (s >= 3) acc = fmaf(w0, base[(size_t)(s - 3) * PQKVZ], acc);
    out[t * CONVD + c] = acc / (1.f + expf(-acc));
}

// ---------------- l2norm(q,k) + gates ----------------
__global__ __launch_bounds__(512) void prep_kernel(const float* __restrict__ conv,
                                                   const float* __restrict__ ba,
                                                   const float* __restrict__ dt_bias,
                                                   const float* __restrict__ A_log,
                                                   float* __restrict__ qn,
                                                   float* __restrict__ kn,
                                                   float* __restrict__ beta,
                                                   float* __restrict__ gdec) {
    size_t t = blockIdx.x;
    int w = threadIdx.x >> 5;
    int l = threadIdx.x & 31;
    const float* cq = conv + t * CONVD + w * DK;
    const float* ck = conv + t * CONVD + KEYD + w * DK;
    float qv[4], kv[4];
    float sq = 0.f, sk = 0.f;
    #pragma unroll
    for (int i = 0; i < 4; i++) {
        qv[i] = cq[l + 32 * i]; sq = fmaf(qv[i], qv[i], sq);
        kv[i] = ck[l + 32 * i]; sk = fmaf(kv[i], kv[i], sk);
    }
    #pragma unroll
    for (int o = 16; o; o >>= 1) {
        sq += __shfl_xor_sync(0xffffffffu, sq, o);
        sk += __shfl_xor_sync(0xffffffffu, sk, o);
    }
    float rq = rsqrtf(sq + EPSF), rk = rsqrtf(sk + EPSF);
    #pragma unroll
    for (int i = 0; i < 4; i++) {
        qn[(t * NK + w) * DK + l + 32 * i] = qv[i] * rq;
        kn[(t * NK + w) * DK + l + 32 * i] = kv[i] * rk;
    }
    if (threadIdx.x < NV) {
        int h = threadIdx.x;
        float bv = ba[t * 64 + h];
        float av = ba[t * 64 + NV + h];
        beta[t * NV + h] = 1.f / (1.f + expf(-bv));
        float xx = av + dt_bias[h];
        float sp = (xx > 20.f) ? xx : log1pf(expf(xx));
        gdec[t * NV + h] = expf(-expf(A_log[h]) * sp);
    }
}

// ---------------- gated delta-rule scan v5 ----------------
#define SCH   8
#define KROW  144   // 4 quarters * 36 floats
__global__ __launch_bounds__(256) void scan_kernel(const float* __restrict__ qn,
                                                   const float* __restrict__ kn,
                                                   const float* __restrict__ conv,
                                                   const float* __restrict__ beta,
                                                   const float* __restrict__ gdec,
                                                   float* __restrict__ core) {
    const int h = blockIdx.x;
    const int dv0 = blockIdx.y * 64;
    const int b = blockIdx.z;
    const int nk = h >> 1;
    const int tid = threadIdx.x;
    const int col = tid >> 2;
    const int quarter = tid & 3;
    __shared__ float ksm[2][SCH][KROW];
    __shared__ float qsm[2][SCH][KROW];
    __shared__ float vsm[2][SCH][64];
    __shared__ float gsm[2][SCH], bsm[2][SCH];

    unsigned long long st[16];
    #pragma unroll
    for (int j = 0; j < 16; j++) st[j] = 0ull;

    const size_t tbase = (size_t)b * SEQ;
    const int krow_t = tid >> 5, kln = tid & 31;
    const int kqoff = (kln >> 3) * 36 + (kln & 7) * 4;

    auto issue = [&](int blk, int buf) {
        const size_t t0 = tbase + (size_t)blk * SCH;
        cpasync16(smem_u32(&ksm[buf][krow_t][kqoff]), kn + ((t0 + krow_t) * NK + nk) * DK + kln * 4);
        cpasync16(smem_u32(&qsm[buf][krow_t][kqoff]), qn + ((t0 + krow_t) * NK + nk) * DK + kln * 4);
        if (tid < 128) {
            int vr = tid >> 4, vc = (tid & 15) * 4;
            cpasync16(smem_u32(&vsm[buf][vr][vc]),
                      conv + (t0 + vr) * CONVD + 2 * KEYD + h * DV + dv0 + vc);
        } else if (tid < 128 + SCH) {
            cpasync4(smem_u32(&gsm[buf][tid - 128]), gdec + (t0 + tid - 128) * NV + h);
        } else if (tid < 128 + 2 * SCH) {
            cpasync4(smem_u32(&bsm[buf][tid - 128 - SCH]), beta + (t0 + tid - 128 - SCH) * NV + h);
        }
    };

    issue(0, 0);
    asm volatile("cp.async.commit_group;" ::: "memory");
    issue(1, 1);
    asm volatile("cp.async.commit_group;" ::: "memory");

    const int nblk = SEQ / SCH;
    for (int blk = 0; blk < nblk; blk++) {
        const int buf = blk & 1;
        asm volatile("cp.async.wait_group 1;" ::: "memory");
        __syncthreads();

        #pragma unroll
        for (int i = 0; i < SCH; i++) {
            const ulonglong2* kk = (const ulonglong2*)&ksm[buf][i][quarter * 36];
            const ulonglong2* qq = (const ulonglong2*)&qsm[buf][i][quarter * 36];
            float vt = vsm[buf][i][col];
            float ge = gsm[buf][i];
            float bt = bsm[buf][i];

            unsigned long long a0 = 0ull, a1 = 0ull;
            #pragma unroll
            for (int j = 0; j < 8; j++) {
                ulonglong2 kj = kk[j];
                a0 = fma2(kj.x, st[2 * j + 0], a0);
                a1 = fma2(kj.y, st[2 * j + 1], a1);
            }
            float kvd = hadd2(a0) + hadd2(a1);
            kvd += __shfl_xor_sync(0xffffffffu, kvd, 1);
            kvd += __shfl_xor_sync(0xffffffffu, kvd, 2);
            float delta = bt * (vt - ge * kvd);
            unsigned long long ge2 = pk2(ge, ge);
            unsigned long long d2 = pk2(delta, delta);

            unsigned long long o0 = 0ull, o1 = 0ull;
            #pragma unroll
            for (int j = 0; j < 8; j++) {
                ulonglong2 kj = kk[j], qj = qq[j];
                st[2 * j + 0] = fma2(ge2, st[2 * j + 0], mul2(kj.x, d2));
                o0 = fma2(qj.x, st[2 * j + 0], o0);
                st[2 * j + 1] = fma2(ge2, st[2 * j + 1], mul2(kj.y, d2));
                o1 = fma2(qj.y, st[2 * j + 1], o1);
            }
            float o = hadd2(o0) + hadd2(o1);
            o += __shfl_xor_sync(0xffffffffu, o, 1);
            o += __shfl_xor_sync(0xffffffffu, o, 2);
            if (quarter == 0)
                core[(tbase + (size_t)blk * SCH + i) * VALD + h * DV + dv0 + col] = o;
        }

        __syncthreads();
        if (blk + 2 < nblk) issue(blk + 2, buf);
        asm volatile("cp.async.commit_group;" ::: "memory");
    }
}

// ---------------- RMSNorm(1+w) + silu(z) gate -> bf16 hi/lo ----------------
__global__ __launch_bounds__(256) void rmsnorm_gate_kernel(const float* __restrict__ core,
                                                           const float* __restrict__ qkvz,
                                                           const float* __restrict__ norm_w,
                                                           __nv_bfloat16* __restrict__ ghi,
                                                           __nv_bfloat16* __restrict__ glo) {
    size_t t = blockIdx.x;
    __shared__ float red[8];
    __shared__ float s_scale;
    const float* row = core + t * VALD;
    const float* zrow = qkvz + t * PQKVZ + 2 * KEYD + VALD;
    float ss = 0.f;
    for (int c = threadIdx.x; c < VALD; c += 256) { float v = row[c]; ss = fmaf(v, v, ss); }
    #pragma unroll
    for (int o = 16; o; o >>= 1) ss += __shfl_xor_sync(0xffffffffu, ss, o);
    if ((threadIdx.x & 31) == 0) red[threadIdx.x >> 5] = ss;
    __syncthreads();
    if (threadIdx.x == 0) {
        float tot = 0.f;
        #pragma unroll
        for (int i = 0; i < 8; i++) tot += red[i];
        s_scale = rsqrtf(tot * (1.f / VALD) + EPSF);
    }
    __syncthreads();
    float sc = s_scale;
    for (int c = threadIdx.x; c < VALD; c += 256) {
        float z = zrow[c];
        float sz = z / (1.f + expf(-z));
        float val = row[c] * sc * (1.f + norm_w[c]) * sz;
        __nv_bfloat16 hv = __float2bfloat16(val);
        ghi[t * VALD + c] = hv;
        glo[t * VALD + c] = __float2bfloat16(val - __bfloat162float(hv));
    }
}

// ---------------- launch (multi-stream capture graph) ----------------
extern "C" void kernel_launch(void* const* d_in, const int* in_sizes, int n_in,
                              void* d_out, int out_size) {
    const float* x       = (const float*)d_in[0];
    const float* W_qkvz  = (const float*)d_in[1];
    const float* W_ba    = (const float*)d_in[2];
    const float* conv_w  = (const float*)d_in[3];
    const float* dt_bias = (const float*)d_in[4];
    const float* A_log   = (const float*)d_in[5];
    const float* norm_w  = (const float*)d_in[6];
    const float* W_out   = (const float*)d_in[7];
    float* out = (float*)d_out;

    float *p_qkvz, *p_ba, *p_conv, *p_qn, *p_kn, *p_beta, *p_g, *p_core;
    __nv_bfloat16 *p_xhi, *p_xlo, *p_w1hi, *p_w1lo, *p_w2hi, *p_w2lo, *p_ghi, *p_glo;
    cudaGetSymbolAddress((void**)&p_qkvz,  g_qkvz);
    cudaGetSymbolAddress((void**)&p_ba,    g_ba);
    cudaGetSymbolAddress((void**)&p_conv,  g_conv);
    cudaGetSymbolAddress((void**)&p_qn,    g_qn);
    cudaGetSymbolAddress((void**)&p_kn,    g_kn);
    cudaGetSymbolAddress((void**)&p_beta,  g_beta);
    cudaGetSymbolAddress((void**)&p_g,     g_gdec);
    cudaGetSymbolAddress((void**)&p_core,  g_core);
    cudaGetSymbolAddress((void**)&p_xhi,  g_xhi);
    cudaGetSymbolAddress((void**)&p_xlo,  g_xlo);
    cudaGetSymbolAddress((void**)&p_w1hi, g_w1hi);
    cudaGetSymbolAddress((void**)&p_w1lo, g_w1lo);
    cudaGetSymbolAddress((void**)&p_w2hi, g_w2hi);
    cudaGetSymbolAddress((void**)&p_w2lo, g_w2lo);
    cudaGetSymbolAddress((void**)&p_ghi,  g_ghi);
    cudaGetSymbolAddress((void**)&p_glo,  g_glo);

    cudaFuncSetAttribute(gemm_bf16x3, cudaFuncAttributeMaxDynamicSharedMemorySize, GSMEM);

    cudaStream_t s2;
    cudaStreamCreateWithFlags(&s2, cudaStreamNonBlocking);
    cudaEvent_t e0, e1a, e1, e2, eprep;
    cudaEventCreateWithFlags(&e0,    cudaEventDisableTiming);
    cudaEventCreateWithFlags(&e1a,   cudaEventDisableTiming);
    cudaEventCreateWithFlags(&e1,    cudaEventDisableTiming);
    cudaEventCreateWithFlags(&e2,    cudaEventDisableTiming);
    cudaEventCreateWithFlags(&eprep, cudaEventDisableTiming);

    // --- fork: s2 joins capture before any work ---
    cudaEventRecord(e0, 0);
    cudaStreamWaitEvent(s2, e0, 0);

    // --- s2: W_out split + ba GEMM (input-only deps) ---
    split_bf16<<<((size_t)HID * VALD) / 1024, 256, 0, s2>>>(W_out, p_w2hi, p_w2lo);
    sgemm_nt<<<dim3(1, TOK / BM), 256, 0, s2>>>(x, W_ba, p_ba, TOK, 64, HID);

    // --- s1: x/W_qkvz splits + GEMM1 qk-half then v-half ---
    split_bf16<<<(TOK * (size_t)HID) / 1024, 256>>>(x, p_xhi, p_xlo);
    split_bf16<<<((size_t)PQKVZ * HID) / 1024, 256>>>(W_qkvz, p_w1hi, p_w1lo);
    gemm_bf16x3<<<dim3(TOK / 128, (2 * KEYD) / 128), 256, GSMEM>>>(
        p_xhi, p_xlo, p_w1hi, p_w1lo, p_qkvz, TOK, 2 * KEYD, HID, PQKVZ);
    cudaEventRecord(e1a, 0);
    gemm_bf16x3<<<dim3(TOK / 128, VALD / 128), 256, GSMEM>>>(
        p_xhi, p_xlo,
        p_w1hi + (size_t)(2 * KEYD) * HID, p_w1lo + (size_t)(2 * KEYD) * HID,
        p_qkvz + 2 * KEYD, TOK, VALD, HID, PQKVZ);
    cudaEventRecord(e1, 0);

    // --- s2: conv(qk channels) + prep overlap GEMM1 v-half ---
    cudaStreamWaitEvent(s2, e1a, 0);
    conv_silu_kernel<<<(TOK * 4096ull) / 256, 256, 0, s2>>>(p_qkvz, conv_w, p_conv, 0);
    prep_kernel<<<TOK, 512, 0, s2>>>(p_conv, p_ba, dt_bias, A_log, p_qn, p_kn, p_beta, p_g);
    cudaEventRecord(eprep, s2);

    // --- s2: z-GEMM after full GEMM1 (avoid tensor-pipe contention); overlaps scan ---
    cudaStreamWaitEvent(s2, e1, 0);
    gemm_bf16x3<<<dim3(TOK / 128, VALD / 128), 256, GSMEM, s2>>>(
        p_xhi, p_xlo,
        p_w1hi + (size_t)CONVD * HID, p_w1lo + (size_t)CONVD * HID,
        p_qkvz + 2 * KEYD + VALD, TOK, VALD, HID, PQKVZ);
    cudaEventRecord(e2, s2);

    // --- s1: conv(v channels) -> scan ---
    conv_silu_kernel<<<(TOK * 4096ull) / 256, 256>>>(p_qkvz, conv_w, p_conv, 2 * KEYD);
    cudaStreamWaitEvent(0, eprep, 0);
    scan_kernel<<<dim3(NV, 2, BATCH), 256>>>(p_qn, p_kn, p_conv, p_beta, p_g, p_core);

    // --- join: rmsnorm needs z columns (merges s2 back) ---
    cudaStreamWaitEvent(0, e2, 0);
    rmsnorm_gate_kernel<<<TOK, 256>>>(p_core, p_qkvz, norm_w, p_ghi, p_glo);
    gemm_bf16x3<<<dim3(TOK / 128, HID / 128), 256, GSMEM>>>(
        p_ghi, p_glo, p_w2hi, p_w2lo, out, TOK, HID, VALD, HID);
}